// round 12
// baseline (speedup 1.0000x reference)
#include <cuda_runtime.h>
#include <cuda_bf16.h>
#include <cstdint>
#include <cstddef>

// ---------------------------------------------------------------------------
// DGCNN pipeline. B=8, N=2048, K=20.
// Round 12: dispatch cleanup on round 11 —
//   * hh3: 8 rows/block + fused layer-1 sq
//   * edge_gather / edge_final: 256-thread blocks, 256/O rows per block
//   * one wtmp_bf_all prep kernel for all 3 layers (per-layer offsets)
// GEMM / select / stats identical to round 11 (983 us, rel_err 3.193e-4).
// ---------------------------------------------------------------------------

#define NPTS   2048
#define NB     8
#define NROWS  (NB*NPTS)   // 16384
#define KNN    20
#define FINF   3.4e38f

// ------------------------- device scratch (no allocs) ----------------------
__device__ float  g_gram[(size_t)NB * NPTS * NPTS];   // reused per layer
__device__ float  g_hh[(size_t)NROWS * 512];          // [rows x 2O], hc | hn
__device__ float  g_hm[(size_t)NROWS * 1024];         // seq features
__device__ float  g_hmax[(size_t)NROWS * 256];
__device__ float  g_hmin[(size_t)NROWS * 256];
__device__ float  g_sq[NROWS];
__device__ int    g_idx[(size_t)NROWS * KNN];
__device__ float  g_wtmp[3 * 128];                    // layer-1 fp32 weights
__device__ float  g_part[(size_t)NROWS * 32];         // per-row group partials
__device__ float  g_mu[128];
__device__ float  g_rs[128];
__device__ float  g_pmax[NB * 8 * 1024];              // seq max partials
__device__ float  g_gvec[NB * 1024];
// bf16 split operands
__device__ __align__(16) __nv_bfloat16 g_ch[(size_t)NROWS * 512];   // concat hi
__device__ __align__(16) __nv_bfloat16 g_cl[(size_t)NROWS * 512];   // concat lo
__device__ __align__(16) __nv_bfloat16 g_wth[512 * 192];            // wtmp^T hi, all layers
__device__ __align__(16) __nv_bfloat16 g_wtl[512 * 192];            // wtmp^T lo
__device__ __align__(16) __nv_bfloat16 g_wmh[1024 * 512];           // wm hi
__device__ __align__(16) __nv_bfloat16 g_wml[1024 * 512];           // wm lo

// per-layer weight offsets in g_wth/g_wtl
#define WOFF_L2 0
#define WOFF_L3 8192
#define WOFF_L4 24576
#define WTOT    90112

__device__ __forceinline__ float leaky02(float v) { return v > 0.f ? v : 0.2f * v; }
__device__ __forceinline__ int   skew(int m)      { return m + (m >> 5); }
#define SD_LEN 2112

__device__ __forceinline__ void split_bf16(float v, __nv_bfloat16& h, __nv_bfloat16& l) {
    h = __float2bfloat16(v);
    l = __float2bfloat16(v - __bfloat162float(h));
}

// --------------------------- cp.async helpers -------------------------------
__device__ __forceinline__ void cp16(void* smem, const void* g) {
    uint32_t s = (uint32_t)__cvta_generic_to_shared(smem);
    asm volatile("cp.async.cg.shared.global [%0], [%1], 16;" :: "r"(s), "l"(g));
}
__device__ __forceinline__ void cp_commit() {
    asm volatile("cp.async.commit_group;");
}
template <int N>
__device__ __forceinline__ void cp_wait() {
    asm volatile("cp.async.wait_group %0;" :: "n"(N));
}

// ================= tensor-core GEMM: pre-split bf16, fp32 accum =============
__device__ __forceinline__ void mma16816(float c[4], const uint32_t a[4],
                                         const uint32_t b[2]) {
    asm volatile(
        "mma.sync.aligned.m16n8k16.row.col.f32.bf16.bf16.f32 "
        "{%0,%1,%2,%3}, {%4,%5,%6,%7}, {%8,%9}, {%0,%1,%2,%3};\n"
        : "+f"(c[0]), "+f"(c[1]), "+f"(c[2]), "+f"(c[3])
        : "r"(a[0]), "r"(a[1]), "r"(a[2]), "r"(a[3]), "r"(b[0]), "r"(b[1]));
}

#define SMS 40                 // smem k-stride in u16 (32 + 8 pad, conflict-free)
#define STAGE_U16 (4 * 128 * SMS)   // Ah|Al|Bh|Bl per stage
#define GEMM_SMEM (2 * STAGE_U16 * 2)  // bytes: 81920

template <bool SYM>
__global__ __launch_bounds__(256, 2) void mmagemm_bf(
    const __nv_bfloat16* __restrict__ pAh, const __nv_bfloat16* __restrict__ pAl,
    int lda, size_t sA,
    const __nv_bfloat16* __restrict__ pBh, const __nv_bfloat16* __restrict__ pBl,
    int ldb, size_t sB,
    float* __restrict__ Cp, int ldc, size_t sC, int K)
{
    extern __shared__ __align__(16) uint16_t dyn[];
    const __nv_bfloat16* Abh = pAh + (size_t)blockIdx.z * sA;
    const __nv_bfloat16* Abl = pAl + (size_t)blockIdx.z * sA;
    const __nv_bfloat16* Bbh = pBh + (size_t)blockIdx.z * sB;
    const __nv_bfloat16* Bbl = pBl + (size_t)blockIdx.z * sB;
    float* Cb = Cp + (size_t)blockIdx.z * sC;

    int m0, n0;
    if (SYM) {
        int i = blockIdx.x;
        int bx = (int)((sqrtf(8.f * (float)i + 1.f) - 1.f) * 0.5f);
        while ((bx + 1) * (bx + 2) / 2 <= i) bx++;
        while (bx * (bx + 1) / 2 > i) bx--;
        int by = i - bx * (bx + 1) / 2;
        m0 = by * 128; n0 = bx * 128;
    } else {
        m0 = blockIdx.y * 128; n0 = blockIdx.x * 128;
    }

    const int tid = threadIdx.x;
    const int warp = tid >> 5, lane = tid & 31;
    const int wrm = warp >> 1, wrn = warp & 1;
    const int g = lane >> 2, q = lane & 3;
    const int row = tid >> 1, c0 = (tid & 1) * 16;

    float acc[2][8][4];
#pragma unroll
    for (int mt = 0; mt < 2; mt++)
#pragma unroll
        for (int nt = 0; nt < 8; nt++)
#pragma unroll
            for (int j = 0; j < 4; j++) acc[mt][nt][j] = 0.f;

    const int nk = K >> 5;

    auto load_stage = [&](int st, int k0) {
        uint16_t* S  = dyn + st * STAGE_U16;
        uint16_t* Ah = S;
        uint16_t* Al = S + 128 * SMS;
        uint16_t* Bh = S + 2 * 128 * SMS;
        uint16_t* Bl = S + 3 * 128 * SMS;
        const size_t aoff = (size_t)(m0 + row) * lda + k0 + c0;
        const size_t boff = (size_t)(n0 + row) * ldb + k0 + c0;
        cp16(&Ah[row * SMS + c0],     &Abh[aoff]);
        cp16(&Ah[row * SMS + c0 + 8], &Abh[aoff + 8]);
        cp16(&Al[row * SMS + c0],     &Abl[aoff]);
        cp16(&Al[row * SMS + c0 + 8], &Abl[aoff + 8]);
        cp16(&Bh[row * SMS + c0],     &Bbh[boff]);
        cp16(&Bh[row * SMS + c0 + 8], &Bbh[boff + 8]);
        cp16(&Bl[row * SMS + c0],     &Bbl[boff]);
        cp16(&Bl[row * SMS + c0 + 8], &Bbl[boff + 8]);
        cp_commit();
    };

    load_stage(0, 0);

    for (int kc = 0; kc < nk; kc++) {
        if (kc + 1 < nk) {
            load_stage((kc + 1) & 1, (kc + 1) << 5);
            cp_wait<1>();
        } else {
            cp_wait<0>();
        }
        __syncthreads();

        uint16_t* S  = dyn + (kc & 1) * STAGE_U16;
        uint16_t* Ah = S;
        uint16_t* Al = S + 128 * SMS;
        uint16_t* Bh = S + 2 * 128 * SMS;
        uint16_t* Bl = S + 3 * 128 * SMS;

#pragma unroll
        for (int ks = 0; ks < 32; ks += 16) {
            const int cb = ks + q * 2;
            uint32_t afh[2][4], afl[2][4];
#pragma unroll
            for (int mt = 0; mt < 2; mt++) {
                int r = wrm * 32 + mt * 16 + g;
                afh[mt][0] = *(const uint32_t*)&Ah[r * SMS + cb];
                afh[mt][1] = *(const uint32_t*)&Ah[(r + 8) * SMS + cb];
                afh[mt][2] = *(const uint32_t*)&Ah[r * SMS + cb + 8];
                afh[mt][3] = *(const uint32_t*)&Ah[(r + 8) * SMS + cb + 8];
                afl[mt][0] = *(const uint32_t*)&Al[r * SMS + cb];
                afl[mt][1] = *(const uint32_t*)&Al[(r + 8) * SMS + cb];
                afl[mt][2] = *(const uint32_t*)&Al[r * SMS + cb + 8];
                afl[mt][3] = *(const uint32_t*)&Al[(r + 8) * SMS + cb + 8];
            }
#pragma unroll
            for (int nt = 0; nt < 8; nt++) {
                int n = wrn * 64 + nt * 8 + g;
                uint32_t bfh[2], bfl[2];
                bfh[0] = *(const uint32_t*)&Bh[n * SMS + cb];
                bfh[1] = *(const uint32_t*)&Bh[n * SMS + cb + 8];
                bfl[0] = *(const uint32_t*)&Bl[n * SMS + cb];
                bfl[1] = *(const uint32_t*)&Bl[n * SMS + cb + 8];
#pragma unroll
                for (int mt = 0; mt < 2; mt++) {
                    mma16816(acc[mt][nt], afh[mt], bfh);
                    mma16816(acc[mt][nt], afh[mt], bfl);
                    mma16816(acc[mt][nt], afl[mt], bfh);
                }
            }
        }
        __syncthreads();
    }

#pragma unroll
    for (int mt = 0; mt < 2; mt++) {
        int r0 = m0 + wrm * 32 + mt * 16 + g;
#pragma unroll
        for (int nt = 0; nt < 8; nt++) {
            int cc = n0 + wrn * 64 + nt * 8 + q * 2;
            *(float2*)&Cb[(size_t)r0 * ldc + cc] =
                make_float2(acc[mt][nt][0], acc[mt][nt][1]);
            *(float2*)&Cb[(size_t)(r0 + 8) * ldc + cc] =
                make_float2(acc[mt][nt][2], acc[mt][nt][3]);
            if (SYM && n0 != m0) {
                Cb[(size_t)cc * ldc + r0]           = acc[mt][nt][0];
                Cb[(size_t)(cc + 1) * ldc + r0]     = acc[mt][nt][1];
                Cb[(size_t)cc * ldc + r0 + 8]       = acc[mt][nt][2];
                Cb[(size_t)(cc + 1) * ldc + r0 + 8] = acc[mt][nt][3];
            }
        }
    }
}

// ============ warp-per-query top-20: redux.sync argmin, skewed smem =========
__device__ __forceinline__ uint32_t fkey(float d) {
    uint32_t b = __float_as_uint(d);
    return (b & 0x80000000u) ? ~b : (b | 0x80000000u);
}

__device__ __forceinline__ void topk_from_smem(uint32_t* sd, int row, int lane,
                                               uint32_t bv, int bi) {
    const unsigned FULL = 0xffffffffu;
#pragma unroll 1
    for (int it = 0; it < KNN; it++) {
        uint32_t gmin = __reduce_min_sync(FULL, bv);
        uint32_t cand = (bv == gmin) ? (uint32_t)bi : 0xffffffffu;
        uint32_t gidx = __reduce_min_sync(FULL, cand);
        if (lane == 0) {
            g_idx[(size_t)row * KNN + it] = (int)gidx;
            sd[skew((int)gidx)] = 0xffffffffu;
        }
        __syncwarp();
        int wl = (int)gidx & 31;
        int m0 = wl + 32 * (2 * lane);
        int m1 = m0 + 32;
        uint32_t d0 = sd[skew(m0)];
        uint32_t d1 = sd[skew(m1)];
        uint32_t rv = d0 < d1 ? d0 : d1;
        int      rb = d0 <= d1 ? m0 : m1;
        uint32_t rmin = __reduce_min_sync(FULL, rv);
        uint32_t cnd2 = (rv == rmin) ? (uint32_t)rb : 0xffffffffu;
        uint32_t ridx = __reduce_min_sync(FULL, cnd2);
        if (lane == wl) { bv = rmin; bi = (int)ridx; }
    }
}

__global__ __launch_bounds__(128) void select_gram_kernel() {
    __shared__ uint32_t sd[4][SD_LEN];
    int warp = threadIdx.x >> 5, lane = threadIdx.x & 31;
    int row = blockIdx.x * 4 + warp;
    int b = row >> 11, n = row & 2047;
    const float* drow = g_gram + (size_t)b * NPTS * NPTS + (size_t)n * NPTS;
    float sqn = g_sq[row];
    uint32_t* sdw = sd[warp];
    uint32_t bv = 0xffffffffu; int bi = 0x7fffffff;
#pragma unroll 8
    for (int j = 0; j < 64; j++) {
        int m = lane + 32 * j;
        float d = sqn + g_sq[(b << 11) + m] - 2.f * drow[m];
        uint32_t k = (m == n) ? 0xffffffffu : fkey(d);
        sdw[skew(m)] = k;
        if (k < bv) { bv = k; bi = m; }
    }
    __syncwarp();
    topk_from_smem(sdw, row, lane, bv, bi);
}

__global__ __launch_bounds__(128) void select3_kernel(const float* __restrict__ X) {
    __shared__ uint32_t sd[4][SD_LEN];
    int warp = threadIdx.x >> 5, lane = threadIdx.x & 31;
    int row = blockIdx.x * 4 + warp;
    int b = row >> 11, n = row & 2047;
    const float* Xb = X + (size_t)(b << 11) * 3;
    float xn = Xb[n * 3], yn = Xb[n * 3 + 1], zn = Xb[n * 3 + 2];
    float sqn = g_sq[row];
    uint32_t* sdw = sd[warp];
    uint32_t bv = 0xffffffffu; int bi = 0x7fffffff;
#pragma unroll 4
    for (int j = 0; j < 64; j++) {
        int m = lane + 32 * j;
        float px = Xb[m * 3], py = Xb[m * 3 + 1], pz = Xb[m * 3 + 2];
        float dot = xn * px + yn * py + zn * pz;
        float d = sqn + g_sq[(b << 11) + m] - 2.f * dot;
        uint32_t k = (m == n) ? 0xffffffffu : fkey(d);
        sdw[skew(m)] = k;
        if (k < bv) { bv = k; bi = m; }
    }
    __syncwarp();
    topk_from_smem(sdw, row, lane, bv, bi);
}

// ------------------- weight transforms (pre-split bf16) --------------------
__global__ void wtmp_kernel(const float* __restrict__ w, int C, int O) {
    int i = blockIdx.x * 256 + threadIdx.x;
    int tot = C * 2 * O;
    if (i < tot) {
        int c = i / (2 * O);
        int o = i % (2 * O);
        float v;
        if (o < O) v = w[(size_t)o * (2 * C) + c] - w[(size_t)o * (2 * C) + C + c];
        else       v = w[(size_t)(o - O) * (2 * C) + C + c];
        g_wtmp[i] = v;
    }
}

// all 3 layers in one launch: transposed [2O][C] bf16 hi/lo at fixed offsets
__global__ void wtmp_bf_all(const float* __restrict__ w2,
                            const float* __restrict__ w3,
                            const float* __restrict__ w4) {
    int i = blockIdx.x * 256 + threadIdx.x;
    if (i >= WTOT) return;
    const float* w; int C, O, rel;
    if (i < WOFF_L3)      { w = w2; C = 64;  O = 64;  rel = i; }
    else if (i < WOFF_L4) { w = w3; C = 64;  O = 128; rel = i - WOFF_L3; }
    else                  { w = w4; C = 128; O = 256; rel = i - WOFF_L4; }
    int o = rel / C, c = rel % C;
    float v;
    if (o < O) v = w[(size_t)o * (2 * C) + c] - w[(size_t)o * (2 * C) + C + c];
    else       v = w[(size_t)(o - O) * (2 * C) + C + c];
    __nv_bfloat16 h, l; split_bf16(v, h, l);
    g_wth[i] = h; g_wtl[i] = l;
}

__global__ void wm_conv_kernel(const float* __restrict__ wm) {
    int i = blockIdx.x * 256 + threadIdx.x;   // 1024*512
    float v = wm[i];
    __nv_bfloat16 h, l; split_bf16(v, h, l);
    g_wmh[i] = h; g_wml[i] = l;
}

// ------------- layer-1 hh (K=3 feature GEMM), 8 rows/block, fused sq --------
__global__ void hh3_kernel(const float* __restrict__ X) {
    __shared__ float w[3 * 128];
    int t = threadIdx.x;   // 128
    w[t] = g_wtmp[t]; w[128 + t] = g_wtmp[128 + t]; w[256 + t] = g_wtmp[256 + t];
    __syncthreads();
    int base = blockIdx.x * 8;
#pragma unroll
    for (int r = 0; r < 8; r++) {
        int row = base + r;
        float x0 = X[row * 3], x1 = X[row * 3 + 1], x2 = X[row * 3 + 2];
        g_hh[(size_t)row * 128 + t] = x0 * w[t] + x1 * w[128 + t] + x2 * w[256 + t];
        if (t == 0) g_sq[row] = x0 * x0 + x1 * x1 + x2 * x2;
    }
}

// ---- fused edge gather: stats + hmax/hmin; 256 threads, 256/O rows/block ---
__global__ __launch_bounds__(256) void edge_gather_kernel(int O) {
    __shared__ int   sidx[4][KNN];
    __shared__ float sacc[4][8];
    const int R = 256 / O;                 // rows per block: 4, 2 or 1
    int rin = threadIdx.x / O;
    int c   = threadIdx.x % O;
    int row = blockIdx.x * R + rin;
    int b = row >> 11;
    if (c < KNN) sidx[rin][c] = g_idx[(size_t)row * KNN + c];
    if (c < 8)  sacc[rin][c] = 0.f;
    __syncthreads();
    int twoO = 2 * O;
    float hcv = g_hh[(size_t)row * twoO + c];
    size_t bbase = ((size_t)(b << 11)) * twoO + O + c;
    float s = 0.f, q = 0.f, mx = -FINF, mn = FINF;
#pragma unroll
    for (int k = 0; k < KNN; k++) {
        float h = hcv + g_hh[bbase + (size_t)sidx[rin][k] * twoO];
        s += h; q += h * h;
        mx = fmaxf(mx, h); mn = fminf(mn, h);
    }
    g_hmax[(size_t)row * O + c] = mx;
    g_hmin[(size_t)row * O + c] = mn;
    int gsz = O >> 2;                      // channels per group
    int rw = gsz < 32 ? gsz : 32;          // reduce width within warp
#pragma unroll
    for (int off = 16; off > 0; off >>= 1) {
        if (off < rw) {
            s += __shfl_down_sync(0xffffffffu, s, off, 32);
            q += __shfl_down_sync(0xffffffffu, q, off, 32);
        }
    }
    int g = c / gsz;
    if ((c & (rw - 1)) == 0 && ((threadIdx.x & 31) % rw) == 0) {
        atomicAdd(&sacc[rin][g * 2 + 0], s);
        atomicAdd(&sacc[rin][g * 2 + 1], q);
    }
    __syncthreads();
    if (c < 8) g_part[(size_t)row * 8 + c] = sacc[rin][c];
}

// ------------------- cross-block stats reduce (edge & seq) ------------------
__global__ __launch_bounds__(256) void stats_reduce_kernel(int perrow, int ngroups,
                                                           float cnt) {
    __shared__ double ds[256], dq[256];
    int g = blockIdx.x, b = blockIdx.y, t = threadIdx.x;
    double s = 0.0, q = 0.0;
    for (int r = t; r < NPTS; r += 256) {
        size_t base = ((size_t)((b << 11) + r)) * perrow + g * 2;
        s += (double)g_part[base];
        q += (double)g_part[base + 1];
    }
    ds[t] = s; dq[t] = q;
    __syncthreads();
    for (int st = 128; st > 0; st >>= 1) {
        if (t < st) { ds[t] += ds[t + st]; dq[t] += dq[t + st]; }
        __syncthreads();
    }
    if (t == 0) {
        double mu = ds[0] / (double)cnt;
        double var = dq[0] / (double)cnt - mu * mu;
        g_mu[b * ngroups + g] = (float)mu;
        g_rs[b * ngroups + g] = rsqrtf((float)var + 1e-5f);
    }
}

// ---- edge final: affine+leaky of hmax/hmin; bf16 hi/lo out + fused sq ------
// 256 threads, 256/O rows per block; sq via warp shfl + smem combine.
__global__ __launch_bounds__(256) void edge_final_kernel(int O, int coff,
                                  const float* __restrict__ gw,
                                  const float* __restrict__ gb) {
    __shared__ float wsum[8];
    const int R = 256 / O;
    int rin = threadIdx.x / O;
    int c   = threadIdx.x % O;
    int row = blockIdx.x * R + rin;
    int b = row >> 11;
    int g = c / (O >> 2);
    float mu = g_mu[b * 4 + g], rs = g_rs[b * 4 + g];
    float a = rs * gw[c];
    float b2 = gb[c] - mu * a;
    float h = (a >= 0.f) ? g_hmax[(size_t)row * O + c] : g_hmin[(size_t)row * O + c];
    float v = leaky02(a * h + b2);
    __nv_bfloat16 vh, vl; split_bf16(v, vh, vl);
    g_ch[(size_t)row * 512 + coff + c] = vh;
    g_cl[(size_t)row * 512 + coff + c] = vl;
    float sq = v * v;
#pragma unroll
    for (int off = 16; off > 0; off >>= 1)
        sq += __shfl_down_sync(0xffffffffu, sq, off);
    int warp = threadIdx.x >> 5;
    if ((threadIdx.x & 31) == 0) wsum[warp] = sq;
    __syncthreads();
    if (c == 0) {
        int w0 = (rin * O) >> 5, nw = O >> 5;
        float s = 0.f;
        for (int i = 0; i < nw; i++) s += wsum[w0 + i];
        g_sq[row] = s;
    }
}

// ------------------------------ seq GN stats --------------------------------
__global__ __launch_bounds__(256) void seq_stats_kernel() {
    __shared__ float sacc[32];
    int row = blockIdx.x;
    int t = threadIdx.x;
    if (t < 32) sacc[t] = 0.f;
    __syncthreads();
    const float* hr = g_hm + (size_t)row * 1024;
    float s = 0.f, q = 0.f;
#pragma unroll
    for (int j = 0; j < 4; j++) { float v = hr[t * 4 + j]; s += v; q += v * v; }
    s += __shfl_down_sync(0xffffffffu, s, 8, 16);
    s += __shfl_down_sync(0xffffffffu, s, 4, 16);
    s += __shfl_down_sync(0xffffffffu, s, 2, 16);
    s += __shfl_down_sync(0xffffffffu, s, 1, 16);
    q += __shfl_down_sync(0xffffffffu, q, 8, 16);
    q += __shfl_down_sync(0xffffffffu, q, 4, 16);
    q += __shfl_down_sync(0xffffffffu, q, 2, 16);
    q += __shfl_down_sync(0xffffffffu, q, 1, 16);
    int g = t >> 4;
    if ((t & 15) == 0) {
        atomicAdd(&sacc[g * 2 + 0], s);
        atomicAdd(&sacc[g * 2 + 1], q);
    }
    __syncthreads();
    if (t < 32) g_part[(size_t)row * 32 + t] = sacc[t];
}

// ------------------- seq normalize + leaky + max over N ---------------------
__global__ __launch_bounds__(256) void seq_max_part(const float* __restrict__ gmw,
                                                    const float* __restrict__ gmb) {
    int c = blockIdx.x * 256 + threadIdx.x;
    int b = blockIdx.y;
    int z = blockIdx.z;
    int g = c >> 6;
    float mu = g_mu[b * 16 + g], rs = g_rs[b * 16 + g];
    float w = gmw[c], bb = gmb[c];
    const float* col = g_hm + ((size_t)b * NPTS + z * 256) * 1024 + c;
    float m = -FINF;
#pragma unroll 4
    for (int n = 0; n < 256; n++) {
        float v = (col[(size_t)n * 1024] - mu) * rs * w + bb;
        m = fmaxf(m, leaky02(v));
    }
    g_pmax[((size_t)b * 8 + z) * 1024 + c] = m;
}

__global__ __launch_bounds__(256) void seq_max_combine() {
    int c = blockIdx.x * 256 + threadIdx.x;
    int b = blockIdx.y;
    float m = -FINF;
#pragma unroll
    for (int z = 0; z < 8; z++)
        m = fmaxf(m, g_pmax[((size_t)b * 8 + z) * 1024 + c]);
    g_gvec[b * 1024 + c] = m;
}

// --------------------------------- MLP head ---------------------------------
__device__ __forceinline__ float bsum256(float v, float* red, int t) {
    red[t] = v; __syncthreads();
    for (int s = 128; s > 0; s >>= 1) {
        if (t < s) red[t] += red[t + s];
        __syncthreads();
    }
    float r = red[0]; __syncthreads();
    return r;
}

__device__ __forceinline__ void ln_leaky(float* buf, int L,
                                         const float* __restrict__ w,
                                         const float* __restrict__ b,
                                         float* red, int t) {
    float s = 0.f, q = 0.f;
    for (int i = t; i < L; i += 256) { float v = buf[i]; s += v; q += v * v; }
    float S = bsum256(s, red, t);
    float Q = bsum256(q, red, t);
    float mu = S / (float)L;
    float var = Q / (float)L - mu * mu;
    float rs = rsqrtf(var + 1e-5f);
    for (int i = t; i < L; i += 256) {
        float v = (buf[i] - mu) * rs * w[i] + b[i];
        buf[i] = leaky02(v);
    }
    __syncthreads();
}

__global__ __launch_bounds__(256) void mlp_kernel(
    const float* __restrict__ fc1w, const float* __restrict__ fc1b,
    const float* __restrict__ ln1w, const float* __restrict__ ln1b,
    const float* __restrict__ fc2w, const float* __restrict__ fc2b,
    const float* __restrict__ ln2w, const float* __restrict__ ln2b,
    const float* __restrict__ fc3w, const float* __restrict__ fc3b,
    const float* __restrict__ ln3w, const float* __restrict__ ln3b,
    const float* __restrict__ fc4w, const float* __restrict__ fc4b,
    float* __restrict__ out)
{
    __shared__ __align__(16) float sin_[1024];
    __shared__ __align__(16) float t1[512];
    __shared__ __align__(16) float t2[256];
    __shared__ __align__(16) float t3[64];
    __shared__ float red[256];
    int b = blockIdx.x, t = threadIdx.x;
    for (int i = t; i < 1024; i += 256) sin_[i] = g_gvec[b * 1024 + i];
    __syncthreads();
    for (int o = t; o < 512; o += 256) {
        float acc = fc1b[o];
        const float4* wr = (const float4*)(fc1w + (size_t)o * 1024);
        const float4* xr = (const float4*)sin_;
        for (int c = 0; c < 256; c++) {
            float4 w4 = wr[c], x4 = xr[c];
            acc += w4.x * x4.x + w4.y * x4.y + w4.z * x4.z + w4.w * x4.w;
        }
        t1[o] = acc;
    }
    __syncthreads();
    ln_leaky(t1, 512, ln1w, ln1b, red, t);
    if (t < 256) {
        float acc = fc2b[t];
        const float4* wr = (const float4*)(fc2w + (size_t)t * 512);
        const float4* xr = (const float4*)t1;
        for (int c = 0; c < 128; c++) {
            float4 w4 = wr[c], x4 = xr[c];
            acc += w4.x * x4.x + w4.y * x4.y + w4.z * x4.z + w4.w * x4.w;
        }
        t2[t] = acc;
    }
    __syncthreads();
    ln_leaky(t2, 256, ln2w, ln2b, red, t);
    if (t < 64) {
        float acc = fc3b[t];
        const float4* wr = (const float4*)(fc3w + (size_t)t * 256);
        const float4* xr = (const float4*)t2;
        for (int c = 0; c < 64; c++) {
            float4 w4 = wr[c], x4 = xr[c];
            acc += w4.x * x4.x + w4.y * x4.y + w4.z * x4.z + w4.w * x4.w;
        }
        t3[t] = acc;
    }
    __syncthreads();
    ln_leaky(t3, 64, ln3w, ln3b, red, t);
    if (t < 2) {
        float acc = fc4b[t];
        for (int c = 0; c < 64; c++) acc += fc4w[t * 64 + c] * t3[c];
        out[b * 2 + t] = acc;
    }
}

// =============================== host driver ================================
extern "C" void kernel_launch(void* const* d_in, const int* in_sizes, int n_in,
                              void* d_out, int out_size)
{
    const float* x    = (const float*)d_in[0];
    const float* w1   = (const float*)d_in[1];
    const float* g1w  = (const float*)d_in[2];
    const float* g1b  = (const float*)d_in[3];
    const float* w2   = (const float*)d_in[4];
    const float* g2w  = (const float*)d_in[5];
    const float* g2b  = (const float*)d_in[6];
    const float* w3   = (const float*)d_in[7];
    const float* g3w  = (const float*)d_in[8];
    const float* g3b  = (const float*)d_in[9];
    const float* w4   = (const float*)d_in[10];
    const float* g4w  = (const float*)d_in[11];
    const float* g4b  = (const float*)d_in[12];
    const float* wm   = (const float*)d_in[13];
    const float* gmw  = (const float*)d_in[14];
    const float* gmb  = (const float*)d_in[15];
    const float* fc1w = (const float*)d_in[16];
    const float* fc1b = (const float*)d_in[17];
    const float* ln1w = (const float*)d_in[18];
    const float* ln1b = (const float*)d_in[19];
    const float* fc2w = (const float*)d_in[20];
    const float* fc2b = (const float*)d_in[21];
    const float* ln2w = (const float*)d_in[22];
    const float* ln2b = (const float*)d_in[23];
    const float* fc3w = (const float*)d_in[24];
    const float* fc3b = (const float*)d_in[25];
    const float* ln3w = (const float*)d_in[26];
    const float* ln3b = (const float*)d_in[27];
    const float* fc4w = (const float*)d_in[28];
    const float* fc4b = (const float*)d_in[29];
    float* out = (float*)d_out;

    float *pGram, *pHH, *pHm;
    __nv_bfloat16 *pCh, *pCl, *pWth, *pWtl, *pWmh, *pWml;
    cudaGetSymbolAddress((void**)&pGram, g_gram);
    cudaGetSymbolAddress((void**)&pHH,   g_hh);
    cudaGetSymbolAddress((void**)&pHm,   g_hm);
    cudaGetSymbolAddress((void**)&pCh,   g_ch);
    cudaGetSymbolAddress((void**)&pCl,   g_cl);
    cudaGetSymbolAddress((void**)&pWth,  g_wth);
    cudaGetSymbolAddress((void**)&pWtl,  g_wtl);
    cudaGetSymbolAddress((void**)&pWmh,  g_wmh);
    cudaGetSymbolAddress((void**)&pWml,  g_wml);

    cudaFuncSetAttribute(mmagemm_bf<true>,
                         cudaFuncAttributeMaxDynamicSharedMemorySize, GEMM_SMEM);
    cudaFuncSetAttribute(mmagemm_bf<false>,
                         cudaFuncAttributeMaxDynamicSharedMemorySize, GEMM_SMEM);

    // -------- weight prep (all layers, up front) ---------------------------
    wm_conv_kernel<<<(1024 * 512) / 256, 256>>>(wm);
    wtmp_bf_all<<<(WTOT + 255) / 256, 256>>>(w2, w3, w4);
    wtmp_kernel<<<(3 * 128 + 255) / 256, 256>>>(w1, 3, 64);

    // ---------------- layer 1 (C=3, O=64) ----------------------------------
    hh3_kernel<<<NROWS / 8, 128>>>(x);                 // also writes g_sq
    select3_kernel<<<NROWS / 4, 128>>>(x);
    edge_gather_kernel<<<NROWS / 4, 256>>>(64);
    stats_reduce_kernel<<<dim3(4, NB), 256>>>(8, 4, (float)(NPTS * KNN * 16));
    edge_final_kernel<<<NROWS / 4, 256>>>(64, 0, g1w, g1b);

    // ---------------- layers 2-4 ------------------------------------------
    struct LayerCfg {
        int coffin;   // input slice offset in g_ch/g_cl
        int C; int O; int woff;
        const float* gw; const float* gb; int coff;
    };
    LayerCfg layers[3] = {
        { 0,   64,  64,  WOFF_L2, g2w, g2b, 64  },
        { 64,  64,  128, WOFF_L3, g3w, g3b, 128 },
        { 128, 128, 256, WOFF_L4, g4w, g4b, 256 },
    };

    const int NTILES = (NPTS / 128) * (NPTS / 128 + 1) / 2;   // 136

    for (int l = 0; l < 3; l++) {
        const LayerCfg& L = layers[l];
        mmagemm_bf<true><<<dim3(NTILES, 1, NB), 256, GEMM_SMEM>>>(
            pCh + L.coffin, pCl + L.coffin, 512, (size_t)NPTS * 512,
            pCh + L.coffin, pCl + L.coffin, 512, (size_t)NPTS * 512,
            pGram, NPTS, (size_t)NPTS * NPTS, L.C);
        select_gram_kernel<<<NROWS / 4, 128>>>();
        mmagemm_bf<false><<<dim3(2 * L.O / 128, NROWS / 128, 1), 256, GEMM_SMEM>>>(
            pCh + L.coffin, pCl + L.coffin, 512, 0,
            pWth + L.woff, pWtl + L.woff, L.C, 0,
            pHH, 2 * L.O, 0, L.C);
        int R = 256 / L.O;
        edge_gather_kernel<<<NROWS / R, 256>>>(L.O);
        stats_reduce_kernel<<<dim3(4, NB), 256>>>(8, 4, (float)(NPTS * KNN * (L.O / 4)));
        edge_final_kernel<<<NROWS / R, 256>>>(L.O, L.coff, L.gw, L.gb);
    }

    // mid: hm = concat @ wm^T  (16384 x 512 -> 1024)
    mmagemm_bf<false><<<dim3(1024 / 128, NROWS / 128, 1), 256, GEMM_SMEM>>>(
        pCh, pCl, 512, 0, pWmh, pWml, 512, 0, pHm, 1024, 0, 512);
    seq_stats_kernel<<<NROWS, 256>>>();
    stats_reduce_kernel<<<dim3(16, NB), 256>>>(32, 16, (float)(NPTS * 64));
    seq_max_part<<<dim3(4, NB, 8), 256>>>(gmw, gmb);
    seq_max_combine<<<dim3(4, NB), 256>>>();

    // head MLP
    mlp_kernel<<<NB, 256>>>(fc1w, fc1b, ln1w, ln1b,
                            fc2w, fc2b, ln2w, ln2b,
                            fc3w, fc3b, ln3w, ln3b,
                            fc4w, fc4b, out);
}

// round 13
// speedup vs baseline: 1.0101x; 1.0101x over previous
#include <cuda_runtime.h>
#include <cuda_bf16.h>
#include <cstdint>
#include <cstddef>

// ---------------------------------------------------------------------------
// DGCNN pipeline. B=8, N=2048, K=20.
// Round 13: mmagemm_bf fragment loads via ldmatrix.m8n8.x4 (24 LDSM replace
// 96 LDS.32 per warp-chunk; identical fragment distribution -> bit-identical
// numerics). Everything else as round 12.
// ---------------------------------------------------------------------------

#define NPTS   2048
#define NB     8
#define NROWS  (NB*NPTS)   // 16384
#define KNN    20
#define FINF   3.4e38f

// ------------------------- device scratch (no allocs) ----------------------
__device__ float  g_gram[(size_t)NB * NPTS * NPTS];   // reused per layer
__device__ float  g_hh[(size_t)NROWS * 512];          // [rows x 2O], hc | hn
__device__ float  g_hm[(size_t)NROWS * 1024];         // seq features
__device__ float  g_hmax[(size_t)NROWS * 256];
__device__ float  g_hmin[(size_t)NROWS * 256];
__device__ float  g_sq[NROWS];
__device__ int    g_idx[(size_t)NROWS * KNN];
__device__ float  g_wtmp[3 * 128];                    // layer-1 fp32 weights
__device__ float  g_part[(size_t)NROWS * 32];         // per-row group partials
__device__ float  g_mu[128];
__device__ float  g_rs[128];
__device__ float  g_pmax[NB * 8 * 1024];              // seq max partials
__device__ float  g_gvec[NB * 1024];
// bf16 split operands
__device__ __align__(16) __nv_bfloat16 g_ch[(size_t)NROWS * 512];   // concat hi
__device__ __align__(16) __nv_bfloat16 g_cl[(size_t)NROWS * 512];   // concat lo
__device__ __align__(16) __nv_bfloat16 g_wth[512 * 192];            // wtmp^T hi, all layers
__device__ __align__(16) __nv_bfloat16 g_wtl[512 * 192];            // wtmp^T lo
__device__ __align__(16) __nv_bfloat16 g_wmh[1024 * 512];           // wm hi
__device__ __align__(16) __nv_bfloat16 g_wml[1024 * 512];           // wm lo

// per-layer weight offsets in g_wth/g_wtl
#define WOFF_L2 0
#define WOFF_L3 8192
#define WOFF_L4 24576
#define WTOT    90112

__device__ __forceinline__ float leaky02(float v) { return v > 0.f ? v : 0.2f * v; }
__device__ __forceinline__ int   skew(int m)      { return m + (m >> 5); }
#define SD_LEN 2112

__device__ __forceinline__ void split_bf16(float v, __nv_bfloat16& h, __nv_bfloat16& l) {
    h = __float2bfloat16(v);
    l = __float2bfloat16(v - __bfloat162float(h));
}

// --------------------------- cp.async helpers -------------------------------
__device__ __forceinline__ void cp16(void* smem, const void* g) {
    uint32_t s = (uint32_t)__cvta_generic_to_shared(smem);
    asm volatile("cp.async.cg.shared.global [%0], [%1], 16;" :: "r"(s), "l"(g));
}
__device__ __forceinline__ void cp_commit() {
    asm volatile("cp.async.commit_group;");
}
template <int N>
__device__ __forceinline__ void cp_wait() {
    asm volatile("cp.async.wait_group %0;" :: "n"(N));
}

// ================= tensor-core GEMM: pre-split bf16, fp32 accum =============
__device__ __forceinline__ void mma16816(float c[4], const uint32_t a[4],
                                         const uint32_t b[2]) {
    asm volatile(
        "mma.sync.aligned.m16n8k16.row.col.f32.bf16.bf16.f32 "
        "{%0,%1,%2,%3}, {%4,%5,%6,%7}, {%8,%9}, {%0,%1,%2,%3};\n"
        : "+f"(c[0]), "+f"(c[1]), "+f"(c[2]), "+f"(c[3])
        : "r"(a[0]), "r"(a[1]), "r"(a[2]), "r"(a[3]), "r"(b[0]), "r"(b[1]));
}

__device__ __forceinline__ void ldsm4(uint32_t r[4], uint32_t saddr) {
    asm volatile(
        "ldmatrix.sync.aligned.m8n8.x4.shared.b16 {%0,%1,%2,%3}, [%4];"
        : "=r"(r[0]), "=r"(r[1]), "=r"(r[2]), "=r"(r[3]) : "r"(saddr));
}

#define SMS 40                 // smem k-stride in u16 (32 + 8 pad, conflict-free)
#define STAGE_U16 (4 * 128 * SMS)   // Ah|Al|Bh|Bl per stage
#define GEMM_SMEM (2 * STAGE_U16 * 2)  // bytes: 81920

template <bool SYM>
__global__ __launch_bounds__(256, 2) void mmagemm_bf(
    const __nv_bfloat16* __restrict__ pAh, const __nv_bfloat16* __restrict__ pAl,
    int lda, size_t sA,
    const __nv_bfloat16* __restrict__ pBh, const __nv_bfloat16* __restrict__ pBl,
    int ldb, size_t sB,
    float* __restrict__ Cp, int ldc, size_t sC, int K)
{
    extern __shared__ __align__(16) uint16_t dyn[];
    const __nv_bfloat16* Abh = pAh + (size_t)blockIdx.z * sA;
    const __nv_bfloat16* Abl = pAl + (size_t)blockIdx.z * sA;
    const __nv_bfloat16* Bbh = pBh + (size_t)blockIdx.z * sB;
    const __nv_bfloat16* Bbl = pBl + (size_t)blockIdx.z * sB;
    float* Cb = Cp + (size_t)blockIdx.z * sC;

    int m0, n0;
    if (SYM) {
        int i = blockIdx.x;
        int bx = (int)((sqrtf(8.f * (float)i + 1.f) - 1.f) * 0.5f);
        while ((bx + 1) * (bx + 2) / 2 <= i) bx++;
        while (bx * (bx + 1) / 2 > i) bx--;
        int by = i - bx * (bx + 1) / 2;
        m0 = by * 128; n0 = bx * 128;
    } else {
        m0 = blockIdx.y * 128; n0 = blockIdx.x * 128;
    }

    const int tid = threadIdx.x;
    const int warp = tid >> 5, lane = tid & 31;
    const int wrm = warp >> 1, wrn = warp & 1;
    const int g = lane >> 2, q = lane & 3;
    const int row = tid >> 1, c0 = (tid & 1) * 16;

    // ldmatrix per-thread row mappings
    const int a_row = lane & 15;                       // A: lanes 0-15 rows 0-15
    const int a_ko  = (lane >> 4) << 3;                //    lanes 16-31: k+8
    const int b_row = (lane & 7) + ((lane >> 4) << 3); // B: n-row within 16-group
    const int b_ko  = ((lane >> 3) & 1) << 3;          //    k offset 0/8

    const uint32_t sbase = (uint32_t)__cvta_generic_to_shared(dyn);

    float acc[2][8][4];
#pragma unroll
    for (int mt = 0; mt < 2; mt++)
#pragma unroll
        for (int nt = 0; nt < 8; nt++)
#pragma unroll
            for (int j = 0; j < 4; j++) acc[mt][nt][j] = 0.f;

    const int nk = K >> 5;

    auto load_stage = [&](int st, int k0) {
        uint16_t* S  = dyn + st * STAGE_U16;
        uint16_t* Ah = S;
        uint16_t* Al = S + 128 * SMS;
        uint16_t* Bh = S + 2 * 128 * SMS;
        uint16_t* Bl = S + 3 * 128 * SMS;
        const size_t aoff = (size_t)(m0 + row) * lda + k0 + c0;
        const size_t boff = (size_t)(n0 + row) * ldb + k0 + c0;
        cp16(&Ah[row * SMS + c0],     &Abh[aoff]);
        cp16(&Ah[row * SMS + c0 + 8], &Abh[aoff + 8]);
        cp16(&Al[row * SMS + c0],     &Abl[aoff]);
        cp16(&Al[row * SMS + c0 + 8], &Abl[aoff + 8]);
        cp16(&Bh[row * SMS + c0],     &Bbh[boff]);
        cp16(&Bh[row * SMS + c0 + 8], &Bbh[boff + 8]);
        cp16(&Bl[row * SMS + c0],     &Bbl[boff]);
        cp16(&Bl[row * SMS + c0 + 8], &Bbl[boff + 8]);
        cp_commit();
    };

    load_stage(0, 0);

    for (int kc = 0; kc < nk; kc++) {
        if (kc + 1 < nk) {
            load_stage((kc + 1) & 1, (kc + 1) << 5);
            cp_wait<1>();
        } else {
            cp_wait<0>();
        }
        __syncthreads();

        const uint32_t S   = sbase + (uint32_t)((kc & 1) * STAGE_U16 * 2);
        const uint32_t sAh = S;
        const uint32_t sAl = S + 128 * SMS * 2;
        const uint32_t sBh = S + 2 * 128 * SMS * 2;
        const uint32_t sBl = S + 3 * 128 * SMS * 2;

#pragma unroll
        for (int ks = 0; ks < 32; ks += 16) {
            uint32_t afh[2][4], afl[2][4];
#pragma unroll
            for (int mt = 0; mt < 2; mt++) {
                uint32_t off = (uint32_t)(((wrm * 32 + mt * 16 + a_row) * SMS
                                           + ks + a_ko) * 2);
                ldsm4(afh[mt], sAh + off);
                ldsm4(afl[mt], sAl + off);
            }
#pragma unroll
            for (int ntp = 0; ntp < 4; ntp++) {
                uint32_t boff = (uint32_t)(((wrn * 64 + ntp * 16 + b_row) * SMS
                                            + ks + b_ko) * 2);
                uint32_t bh[4], bl[4];
                ldsm4(bh, sBh + boff);
                ldsm4(bl, sBl + boff);
#pragma unroll
                for (int half = 0; half < 2; half++) {
                    int nt = 2 * ntp + half;
#pragma unroll
                    for (int mt = 0; mt < 2; mt++) {
                        mma16816(acc[mt][nt], afh[mt], &bh[half * 2]);
                        mma16816(acc[mt][nt], afh[mt], &bl[half * 2]);
                        mma16816(acc[mt][nt], afl[mt], &bh[half * 2]);
                    }
                }
            }
        }
        __syncthreads();
    }

#pragma unroll
    for (int mt = 0; mt < 2; mt++) {
        int r0 = m0 + wrm * 32 + mt * 16 + g;
#pragma unroll
        for (int nt = 0; nt < 8; nt++) {
            int cc = n0 + wrn * 64 + nt * 8 + q * 2;
            *(float2*)&Cb[(size_t)r0 * ldc + cc] =
                make_float2(acc[mt][nt][0], acc[mt][nt][1]);
            *(float2*)&Cb[(size_t)(r0 + 8) * ldc + cc] =
                make_float2(acc[mt][nt][2], acc[mt][nt][3]);
            if (SYM && n0 != m0) {
                Cb[(size_t)cc * ldc + r0]           = acc[mt][nt][0];
                Cb[(size_t)(cc + 1) * ldc + r0]     = acc[mt][nt][1];
                Cb[(size_t)cc * ldc + r0 + 8]       = acc[mt][nt][2];
                Cb[(size_t)(cc + 1) * ldc + r0 + 8] = acc[mt][nt][3];
            }
        }
    }
}

// ============ warp-per-query top-20: redux.sync argmin, skewed smem =========
__device__ __forceinline__ uint32_t fkey(float d) {
    uint32_t b = __float_as_uint(d);
    return (b & 0x80000000u) ? ~b : (b | 0x80000000u);
}

__device__ __forceinline__ void topk_from_smem(uint32_t* sd, int row, int lane,
                                               uint32_t bv, int bi) {
    const unsigned FULL = 0xffffffffu;
#pragma unroll 1
    for (int it = 0; it < KNN; it++) {
        uint32_t gmin = __reduce_min_sync(FULL, bv);
        uint32_t cand = (bv == gmin) ? (uint32_t)bi : 0xffffffffu;
        uint32_t gidx = __reduce_min_sync(FULL, cand);
        if (lane == 0) {
            g_idx[(size_t)row * KNN + it] = (int)gidx;
            sd[skew((int)gidx)] = 0xffffffffu;
        }
        __syncwarp();
        int wl = (int)gidx & 31;
        int m0 = wl + 32 * (2 * lane);
        int m1 = m0 + 32;
        uint32_t d0 = sd[skew(m0)];
        uint32_t d1 = sd[skew(m1)];
        uint32_t rv = d0 < d1 ? d0 : d1;
        int      rb = d0 <= d1 ? m0 : m1;
        uint32_t rmin = __reduce_min_sync(FULL, rv);
        uint32_t cnd2 = (rv == rmin) ? (uint32_t)rb : 0xffffffffu;
        uint32_t ridx = __reduce_min_sync(FULL, cnd2);
        if (lane == wl) { bv = rmin; bi = (int)ridx; }
    }
}

__global__ __launch_bounds__(128) void select_gram_kernel() {
    __shared__ uint32_t sd[4][SD_LEN];
    int warp = threadIdx.x >> 5, lane = threadIdx.x & 31;
    int row = blockIdx.x * 4 + warp;
    int b = row >> 11, n = row & 2047;
    const float* drow = g_gram + (size_t)b * NPTS * NPTS + (size_t)n * NPTS;
    float sqn = g_sq[row];
    uint32_t* sdw = sd[warp];
    uint32_t bv = 0xffffffffu; int bi = 0x7fffffff;
#pragma unroll 8
    for (int j = 0; j < 64; j++) {
        int m = lane + 32 * j;
        float d = sqn + g_sq[(b << 11) + m] - 2.f * drow[m];
        uint32_t k = (m == n) ? 0xffffffffu : fkey(d);
        sdw[skew(m)] = k;
        if (k < bv) { bv = k; bi = m; }
    }
    __syncwarp();
    topk_from_smem(sdw, row, lane, bv, bi);
}

__global__ __launch_bounds__(128) void select3_kernel(const float* __restrict__ X) {
    __shared__ uint32_t sd[4][SD_LEN];
    int warp = threadIdx.x >> 5, lane = threadIdx.x & 31;
    int row = blockIdx.x * 4 + warp;
    int b = row >> 11, n = row & 2047;
    const float* Xb = X + (size_t)(b << 11) * 3;
    float xn = Xb[n * 3], yn = Xb[n * 3 + 1], zn = Xb[n * 3 + 2];
    float sqn = g_sq[row];
    uint32_t* sdw = sd[warp];
    uint32_t bv = 0xffffffffu; int bi = 0x7fffffff;
#pragma unroll 4
    for (int j = 0; j < 64; j++) {
        int m = lane + 32 * j;
        float px = Xb[m * 3], py = Xb[m * 3 + 1], pz = Xb[m * 3 + 2];
        float dot = xn * px + yn * py + zn * pz;
        float d = sqn + g_sq[(b << 11) + m] - 2.f * dot;
        uint32_t k = (m == n) ? 0xffffffffu : fkey(d);
        sdw[skew(m)] = k;
        if (k < bv) { bv = k; bi = m; }
    }
    __syncwarp();
    topk_from_smem(sdw, row, lane, bv, bi);
}

// ------------------- weight transforms (pre-split bf16) --------------------
__global__ void wtmp_kernel(const float* __restrict__ w, int C, int O) {
    int i = blockIdx.x * 256 + threadIdx.x;
    int tot = C * 2 * O;
    if (i < tot) {
        int c = i / (2 * O);
        int o = i % (2 * O);
        float v;
        if (o < O) v = w[(size_t)o * (2 * C) + c] - w[(size_t)o * (2 * C) + C + c];
        else       v = w[(size_t)(o - O) * (2 * C) + C + c];
        g_wtmp[i] = v;
    }
}

__global__ void wtmp_bf_all(const float* __restrict__ w2,
                            const float* __restrict__ w3,
                            const float* __restrict__ w4) {
    int i = blockIdx.x * 256 + threadIdx.x;
    if (i >= WTOT) return;
    const float* w; int C, O, rel;
    if (i < WOFF_L3)      { w = w2; C = 64;  O = 64;  rel = i; }
    else if (i < WOFF_L4) { w = w3; C = 64;  O = 128; rel = i - WOFF_L3; }
    else                  { w = w4; C = 128; O = 256; rel = i - WOFF_L4; }
    int o = rel / C, c = rel % C;
    float v;
    if (o < O) v = w[(size_t)o * (2 * C) + c] - w[(size_t)o * (2 * C) + C + c];
    else       v = w[(size_t)(o - O) * (2 * C) + C + c];
    __nv_bfloat16 h, l; split_bf16(v, h, l);
    g_wth[i] = h; g_wtl[i] = l;
}

__global__ void wm_conv_kernel(const float* __restrict__ wm) {
    int i = blockIdx.x * 256 + threadIdx.x;   // 1024*512
    float v = wm[i];
    __nv_bfloat16 h, l; split_bf16(v, h, l);
    g_wmh[i] = h; g_wml[i] = l;
}

// ------------- layer-1 hh (K=3 feature GEMM), 8 rows/block, fused sq --------
__global__ void hh3_kernel(const float* __restrict__ X) {
    __shared__ float w[3 * 128];
    int t = threadIdx.x;   // 128
    w[t] = g_wtmp[t]; w[128 + t] = g_wtmp[128 + t]; w[256 + t] = g_wtmp[256 + t];
    __syncthreads();
    int base = blockIdx.x * 8;
#pragma unroll
    for (int r = 0; r < 8; r++) {
        int row = base + r;
        float x0 = X[row * 3], x1 = X[row * 3 + 1], x2 = X[row * 3 + 2];
        g_hh[(size_t)row * 128 + t] = x0 * w[t] + x1 * w[128 + t] + x2 * w[256 + t];
        if (t == 0) g_sq[row] = x0 * x0 + x1 * x1 + x2 * x2;
    }
}

// ---- fused edge gather: stats + hmax/hmin; 256 threads, 256/O rows/block ---
__global__ __launch_bounds__(256) void edge_gather_kernel(int O) {
    __shared__ int   sidx[4][KNN];
    __shared__ float sacc[4][8];
    const int R = 256 / O;
    int rin = threadIdx.x / O;
    int c   = threadIdx.x % O;
    int row = blockIdx.x * R + rin;
    int b = row >> 11;
    if (c < KNN) sidx[rin][c] = g_idx[(size_t)row * KNN + c];
    if (c < 8)  sacc[rin][c] = 0.f;
    __syncthreads();
    int twoO = 2 * O;
    float hcv = g_hh[(size_t)row * twoO + c];
    size_t bbase = ((size_t)(b << 11)) * twoO + O + c;
    float s = 0.f, q = 0.f, mx = -FINF, mn = FINF;
#pragma unroll
    for (int k = 0; k < KNN; k++) {
        float h = hcv + g_hh[bbase + (size_t)sidx[rin][k] * twoO];
        s += h; q += h * h;
        mx = fmaxf(mx, h); mn = fminf(mn, h);
    }
    g_hmax[(size_t)row * O + c] = mx;
    g_hmin[(size_t)row * O + c] = mn;
    int gsz = O >> 2;
    int rw = gsz < 32 ? gsz : 32;
#pragma unroll
    for (int off = 16; off > 0; off >>= 1) {
        if (off < rw) {
            s += __shfl_down_sync(0xffffffffu, s, off, 32);
            q += __shfl_down_sync(0xffffffffu, q, off, 32);
        }
    }
    int g = c / gsz;
    if ((c & (rw - 1)) == 0 && ((threadIdx.x & 31) % rw) == 0) {
        atomicAdd(&sacc[rin][g * 2 + 0], s);
        atomicAdd(&sacc[rin][g * 2 + 1], q);
    }
    __syncthreads();
    if (c < 8) g_part[(size_t)row * 8 + c] = sacc[rin][c];
}

// ------------------- cross-block stats reduce (edge & seq) ------------------
__global__ __launch_bounds__(256) void stats_reduce_kernel(int perrow, int ngroups,
                                                           float cnt) {
    __shared__ double ds[256], dq[256];
    int g = blockIdx.x, b = blockIdx.y, t = threadIdx.x;
    double s = 0.0, q = 0.0;
    for (int r = t; r < NPTS; r += 256) {
        size_t base = ((size_t)((b << 11) + r)) * perrow + g * 2;
        s += (double)g_part[base];
        q += (double)g_part[base + 1];
    }
    ds[t] = s; dq[t] = q;
    __syncthreads();
    for (int st = 128; st > 0; st >>= 1) {
        if (t < st) { ds[t] += ds[t + st]; dq[t] += dq[t + st]; }
        __syncthreads();
    }
    if (t == 0) {
        double mu = ds[0] / (double)cnt;
        double var = dq[0] / (double)cnt - mu * mu;
        g_mu[b * ngroups + g] = (float)mu;
        g_rs[b * ngroups + g] = rsqrtf((float)var + 1e-5f);
    }
}

// ---- edge final: affine+leaky of hmax/hmin; bf16 hi/lo out + fused sq ------
__global__ __launch_bounds__(256) void edge_final_kernel(int O, int coff,
                                  const float* __restrict__ gw,
                                  const float* __restrict__ gb) {
    __shared__ float wsum[8];
    const int R = 256 / O;
    int rin = threadIdx.x / O;
    int c   = threadIdx.x % O;
    int row = blockIdx.x * R + rin;
    int b = row >> 11;
    int g = c / (O >> 2);
    float mu = g_mu[b * 4 + g], rs = g_rs[b * 4 + g];
    float a = rs * gw[c];
    float b2 = gb[c] - mu * a;
    float h = (a >= 0.f) ? g_hmax[(size_t)row * O + c] : g_hmin[(size_t)row * O + c];
    float v = leaky02(a * h + b2);
    __nv_bfloat16 vh, vl; split_bf16(v, vh, vl);
    g_ch[(size_t)row * 512 + coff + c] = vh;
    g_cl[(size_t)row * 512 + coff + c] = vl;
    float sq = v * v;
#pragma unroll
    for (int off = 16; off > 0; off >>= 1)
        sq += __shfl_down_sync(0xffffffffu, sq, off);
    int warp = threadIdx.x >> 5;
    if ((threadIdx.x & 31) == 0) wsum[warp] = sq;
    __syncthreads();
    if (c == 0) {
        int w0 = (rin * O) >> 5, nw = O >> 5;
        float s = 0.f;
        for (int i = 0; i < nw; i++) s += wsum[w0 + i];
        g_sq[row] = s;
    }
}

// ------------------------------ seq GN stats --------------------------------
__global__ __launch_bounds__(256) void seq_stats_kernel() {
    __shared__ float sacc[32];
    int row = blockIdx.x;
    int t = threadIdx.x;
    if (t < 32) sacc[t] = 0.f;
    __syncthreads();
    const float* hr = g_hm + (size_t)row * 1024;
    float s = 0.f, q = 0.f;
#pragma unroll
    for (int j = 0; j < 4; j++) { float v = hr[t * 4 + j]; s += v; q += v * v; }
    s += __shfl_down_sync(0xffffffffu, s, 8, 16);
    s += __shfl_down_sync(0xffffffffu, s, 4, 16);
    s += __shfl_down_sync(0xffffffffu, s, 2, 16);
    s += __shfl_down_sync(0xffffffffu, s, 1, 16);
    q += __shfl_down_sync(0xffffffffu, q, 8, 16);
    q += __shfl_down_sync(0xffffffffu, q, 4, 16);
    q += __shfl_down_sync(0xffffffffu, q, 2, 16);
    q += __shfl_down_sync(0xffffffffu, q, 1, 16);
    int g = t >> 4;
    if ((t & 15) == 0) {
        atomicAdd(&sacc[g * 2 + 0], s);
        atomicAdd(&sacc[g * 2 + 1], q);
    }
    __syncthreads();
    if (t < 32) g_part[(size_t)row * 32 + t] = sacc[t];
}

// ------------------- seq normalize + leaky + max over N ---------------------
__global__ __launch_bounds__(256) void seq_max_part(const float* __restrict__ gmw,
                                                    const float* __restrict__ gmb) {
    int c = blockIdx.x * 256 + threadIdx.x;
    int b = blockIdx.y;
    int z = blockIdx.z;
    int g = c >> 6;
    float mu = g_mu[b * 16 + g], rs = g_rs[b * 16 + g];
    float w = gmw[c], bb = gmb[c];
    const float* col = g_hm + ((size_t)b * NPTS + z * 256) * 1024 + c;
    float m = -FINF;
#pragma unroll 4
    for (int n = 0; n < 256; n++) {
        float v = (col[(size_t)n * 1024] - mu) * rs * w + bb;
        m = fmaxf(m, leaky02(v));
    }
    g_pmax[((size_t)b * 8 + z) * 1024 + c] = m;
}

__global__ __launch_bounds__(256) void seq_max_combine() {
    int c = blockIdx.x * 256 + threadIdx.x;
    int b = blockIdx.y;
    float m = -FINF;
#pragma unroll
    for (int z = 0; z < 8; z++)
        m = fmaxf(m, g_pmax[((size_t)b * 8 + z) * 1024 + c]);
    g_gvec[b * 1024 + c] = m;
}

// --------------------------------- MLP head ---------------------------------
__device__ __forceinline__ float bsum256(float v, float* red, int t) {
    red[t] = v; __syncthreads();
    for (int s = 128; s > 0; s >>= 1) {
        if (t < s) red[t] += red[t + s];
        __syncthreads();
    }
    float r = red[0]; __syncthreads();
    return r;
}

__device__ __forceinline__ void ln_leaky(float* buf, int L,
                                         const float* __restrict__ w,
                                         const float* __restrict__ b,
                                         float* red, int t) {
    float s = 0.f, q = 0.f;
    for (int i = t; i < L; i += 256) { float v = buf[i]; s += v; q += v * v; }
    float S = bsum256(s, red, t);
    float Q = bsum256(q, red, t);
    float mu = S / (float)L;
    float var = Q / (float)L - mu * mu;
    float rs = rsqrtf(var + 1e-5f);
    for (int i = t; i < L; i += 256) {
        float v = (buf[i] - mu) * rs * w[i] + b[i];
        buf[i] = leaky02(v);
    }
    __syncthreads();
}

__global__ __launch_bounds__(256) void mlp_kernel(
    const float* __restrict__ fc1w, const float* __restrict__ fc1b,
    const float* __restrict__ ln1w, const float* __restrict__ ln1b,
    const float* __restrict__ fc2w, const float* __restrict__ fc2b,
    const float* __restrict__ ln2w, const float* __restrict__ ln2b,
    const float* __restrict__ fc3w, const float* __restrict__ fc3b,
    const float* __restrict__ ln3w, const float* __restrict__ ln3b,
    const float* __restrict__ fc4w, const float* __restrict__ fc4b,
    float* __restrict__ out)
{
    __shared__ __align__(16) float sin_[1024];
    __shared__ __align__(16) float t1[512];
    __shared__ __align__(16) float t2[256];
    __shared__ __align__(16) float t3[64];
    __shared__ float red[256];
    int b = blockIdx.x, t = threadIdx.x;
    for (int i = t; i < 1024; i += 256) sin_[i] = g_gvec[b * 1024 + i];
    __syncthreads();
    for (int o = t; o < 512; o += 256) {
        float acc = fc1b[o];
        const float4* wr = (const float4*)(fc1w + (size_t)o * 1024);
        const float4* xr = (const float4*)sin_;
        for (int c = 0; c < 256; c++) {
            float4 w4 = wr[c], x4 = xr[c];
            acc += w4.x * x4.x + w4.y * x4.y + w4.z * x4.z + w4.w * x4.w;
        }
        t1[o] = acc;
    }
    __syncthreads();
    ln_leaky(t1, 512, ln1w, ln1b, red, t);
    if (t < 256) {
        float acc = fc2b[t];
        const float4* wr = (const float4*)(fc2w + (size_t)t * 512);
        const float4* xr = (const float4*)t1;
        for (int c = 0; c < 128; c++) {
            float4 w4 = wr[c], x4 = xr[c];
            acc += w4.x * x4.x + w4.y * x4.y + w4.z * x4.z + w4.w * x4.w;
        }
        t2[t] = acc;
    }
    __syncthreads();
    ln_leaky(t2, 256, ln2w, ln2b, red, t);
    if (t < 64) {
        float acc = fc3b[t];
        const float4* wr = (const float4*)(fc3w + (size_t)t * 256);
        const float4* xr = (const float4*)t2;
        for (int c = 0; c < 64; c++) {
            float4 w4 = wr[c], x4 = xr[c];
            acc += w4.x * x4.x + w4.y * x4.y + w4.z * x4.z + w4.w * x4.w;
        }
        t3[t] = acc;
    }
    __syncthreads();
    ln_leaky(t3, 64, ln3w, ln3b, red, t);
    if (t < 2) {
        float acc = fc4b[t];
        for (int c = 0; c < 64; c++) acc += fc4w[t * 64 + c] * t3[c];
        out[b * 2 + t] = acc;
    }
}

// =============================== host driver ================================
extern "C" void kernel_launch(void* const* d_in, const int* in_sizes, int n_in,
                              void* d_out, int out_size)
{
    const float* x    = (const float*)d_in[0];
    const float* w1   = (const float*)d_in[1];
    const float* g1w  = (const float*)d_in[2];
    const float* g1b  = (const float*)d_in[3];
    const float* w2   = (const float*)d_in[4];
    const float* g2w  = (const float*)d_in[5];
    const float* g2b  = (const float*)d_in[6];
    const float* w3   = (const float*)d_in[7];
    const float* g3w  = (const float*)d_in[8];
    const float* g3b  = (const float*)d_in[9];
    const float* w4   = (const float*)d_in[10];
    const float* g4w  = (const float*)d_in[11];
    const float* g4b  = (const float*)d_in[12];
    const float* wm   = (const float*)d_in[13];
    const float* gmw  = (const float*)d_in[14];
    const float* gmb  = (const float*)d_in[15];
    const float* fc1w = (const float*)d_in[16];
    const float* fc1b = (const float*)d_in[17];
    const float* ln1w = (const float*)d_in[18];
    const float* ln1b = (const float*)d_in[19];
    const float* fc2w = (const float*)d_in[20];
    const float* fc2b = (const float*)d_in[21];
    const float* ln2w = (const float*)d_in[22];
    const float* ln2b = (const float*)d_in[23];
    const float* fc3w = (const float*)d_in[24];
    const float* fc3b = (const float*)d_in[25];
    const float* ln3w = (const float*)d_in[26];
    const float* ln3b = (const float*)d_in[27];
    const float* fc4w = (const float*)d_in[28];
    const float* fc4b = (const float*)d_in[29];
    float* out = (float*)d_out;

    float *pGram, *pHH, *pHm;
    __nv_bfloat16 *pCh, *pCl, *pWth, *pWtl, *pWmh, *pWml;
    cudaGetSymbolAddress((void**)&pGram, g_gram);
    cudaGetSymbolAddress((void**)&pHH,   g_hh);
    cudaGetSymbolAddress((void**)&pHm,   g_hm);
    cudaGetSymbolAddress((void**)&pCh,   g_ch);
    cudaGetSymbolAddress((void**)&pCl,   g_cl);
    cudaGetSymbolAddress((void**)&pWth,  g_wth);
    cudaGetSymbolAddress((void**)&pWtl,  g_wtl);
    cudaGetSymbolAddress((void**)&pWmh,  g_wmh);
    cudaGetSymbolAddress((void**)&pWml,  g_wml);

    cudaFuncSetAttribute(mmagemm_bf<true>,
                         cudaFuncAttributeMaxDynamicSharedMemorySize, GEMM_SMEM);
    cudaFuncSetAttribute(mmagemm_bf<false>,
                         cudaFuncAttributeMaxDynamicSharedMemorySize, GEMM_SMEM);

    // -------- weight prep (all layers, up front) ---------------------------
    wm_conv_kernel<<<(1024 * 512) / 256, 256>>>(wm);
    wtmp_bf_all<<<(WTOT + 255) / 256, 256>>>(w2, w3, w4);
    wtmp_kernel<<<(3 * 128 + 255) / 256, 256>>>(w1, 3, 64);

    // ---------------- layer 1 (C=3, O=64) ----------------------------------
    hh3_kernel<<<NROWS / 8, 128>>>(x);                 // also writes g_sq
    select3_kernel<<<NROWS / 4, 128>>>(x);
    edge_gather_kernel<<<NROWS / 4, 256>>>(64);
    stats_reduce_kernel<<<dim3(4, NB), 256>>>(8, 4, (float)(NPTS * KNN * 16));
    edge_final_kernel<<<NROWS / 4, 256>>>(64, 0, g1w, g1b);

    // ---------------- layers 2-4 ------------------------------------------
    struct LayerCfg {
        int coffin;   // input slice offset in g_ch/g_cl
        int C; int O; int woff;
        const float* gw; const float* gb; int coff;
    };
    LayerCfg layers[3] = {
        { 0,   64,  64,  WOFF_L2, g2w, g2b, 64  },
        { 64,  64,  128, WOFF_L3, g3w, g3b, 128 },
        { 128, 128, 256, WOFF_L4, g4w, g4b, 256 },
    };

    const int NTILES = (NPTS / 128) * (NPTS / 128 + 1) / 2;   // 136

    for (int l = 0; l < 3; l++) {
        const LayerCfg& L = layers[l];
        mmagemm_bf<true><<<dim3(NTILES, 1, NB), 256, GEMM_SMEM>>>(
            pCh + L.coffin, pCl + L.coffin, 512, (size_t)NPTS * 512,
            pCh + L.coffin, pCl + L.coffin, 512, (size_t)NPTS * 512,
            pGram, NPTS, (size_t)NPTS * NPTS, L.C);
        select_gram_kernel<<<NROWS / 4, 128>>>();
        mmagemm_bf<false><<<dim3(2 * L.O / 128, NROWS / 128, 1), 256, GEMM_SMEM>>>(
            pCh + L.coffin, pCl + L.coffin, 512, 0,
            pWth + L.woff, pWtl + L.woff, L.C, 0,
            pHH, 2 * L.O, 0, L.C);
        int R = 256 / L.O;
        edge_gather_kernel<<<NROWS / R, 256>>>(L.O);
        stats_reduce_kernel<<<dim3(4, NB), 256>>>(8, 4, (float)(NPTS * KNN * (L.O / 4)));
        edge_final_kernel<<<NROWS / R, 256>>>(L.O, L.coff, L.gw, L.gb);
    }

    // mid: hm = concat @ wm^T  (16384 x 512 -> 1024)
    mmagemm_bf<false><<<dim3(1024 / 128, NROWS / 128, 1), 256, GEMM_SMEM>>>(
        pCh, pCl, 512, 0, pWmh, pWml, 512, 0, pHm, 1024, 0, 512);
    seq_stats_kernel<<<NROWS, 256>>>();
    stats_reduce_kernel<<<dim3(16, NB), 256>>>(32, 16, (float)(NPTS * 64));
    seq_max_part<<<dim3(4, NB, 8), 256>>>(gmw, gmb);
    seq_max_combine<<<dim3(4, NB), 256>>>();

    // head MLP
    mlp_kernel<<<NB, 256>>>(fc1w, fc1b, ln1w, ln1b,
                            fc2w, fc2b, ln2w, ln2b,
                            fc3w, fc3b, ln3w, ln3b,
                            fc4w, fc4b, out);
}

// round 14
// speedup vs baseline: 1.0686x; 1.0579x over previous
#include <cuda_runtime.h>
#include <cuda_bf16.h>
#include <cstdint>
#include <cstddef>

// ---------------------------------------------------------------------------
// DGCNN pipeline. B=8, N=2048, K=20.
// Round 14: wm GEMM fused with the whole seq pipeline. The 16384x1024 hm
// tensor is never materialized: the GEMM epilogue reduces each 128x128 tile
// to per-column {max,min,sum,sumsq} partials; seq_final combines partials,
// computes GN16 stats, and emits gvec directly (monotone leaky(a*h+b) trick).
// Removes seq_stats / seq_max_part / seq_max_combine and ~200MB of traffic.
// Everything else as round 13 (975 us, rel_err 3.193e-4).
// ---------------------------------------------------------------------------

#define NPTS   2048
#define NB     8
#define NROWS  (NB*NPTS)   // 16384
#define KNN    20
#define FINF   3.4e38f

// ------------------------- device scratch (no allocs) ----------------------
__device__ float  g_gram[(size_t)NB * NPTS * NPTS];   // reused per layer
__device__ float  g_hh[(size_t)NROWS * 512];          // [rows x 2O], hc | hn
__device__ float  g_hmax[(size_t)NROWS * 256];
__device__ float  g_hmin[(size_t)NROWS * 256];
__device__ float  g_sq[NROWS];
__device__ int    g_idx[(size_t)NROWS * KNN];
__device__ float  g_wtmp[3 * 128];                    // layer-1 fp32 weights
__device__ float  g_part[(size_t)NROWS * 32];         // per-row group partials
__device__ float  g_mu[128];
__device__ float  g_rs[128];
__device__ float  g_ep[4 * 128 * 1024];               // wm tile partials
__device__ float  g_gvec[NB * 1024];
// bf16 split operands
__device__ __align__(16) __nv_bfloat16 g_ch[(size_t)NROWS * 512];   // concat hi
__device__ __align__(16) __nv_bfloat16 g_cl[(size_t)NROWS * 512];   // concat lo
__device__ __align__(16) __nv_bfloat16 g_wth[512 * 192];            // wtmp^T hi, all layers
__device__ __align__(16) __nv_bfloat16 g_wtl[512 * 192];            // wtmp^T lo
__device__ __align__(16) __nv_bfloat16 g_wmh[1024 * 512];           // wm hi
__device__ __align__(16) __nv_bfloat16 g_wml[1024 * 512];           // wm lo

// per-layer weight offsets in g_wth/g_wtl
#define WOFF_L2 0
#define WOFF_L3 8192
#define WOFF_L4 24576
#define WTOT    90112

__device__ __forceinline__ float leaky02(float v) { return v > 0.f ? v : 0.2f * v; }
__device__ __forceinline__ int   skew(int m)      { return m + (m >> 5); }
#define SD_LEN 2112

__device__ __forceinline__ void split_bf16(float v, __nv_bfloat16& h, __nv_bfloat16& l) {
    h = __float2bfloat16(v);
    l = __float2bfloat16(v - __bfloat162float(h));
}

// --------------------------- cp.async helpers -------------------------------
__device__ __forceinline__ void cp16(void* smem, const void* g) {
    uint32_t s = (uint32_t)__cvta_generic_to_shared(smem);
    asm volatile("cp.async.cg.shared.global [%0], [%1], 16;" :: "r"(s), "l"(g));
}
__device__ __forceinline__ void cp_commit() {
    asm volatile("cp.async.commit_group;");
}
template <int N>
__device__ __forceinline__ void cp_wait() {
    asm volatile("cp.async.wait_group %0;" :: "n"(N));
}

// ================= tensor-core GEMM: pre-split bf16, fp32 accum =============
__device__ __forceinline__ void mma16816(float c[4], const uint32_t a[4],
                                         const uint32_t b[2]) {
    asm volatile(
        "mma.sync.aligned.m16n8k16.row.col.f32.bf16.bf16.f32 "
        "{%0,%1,%2,%3}, {%4,%5,%6,%7}, {%8,%9}, {%0,%1,%2,%3};\n"
        : "+f"(c[0]), "+f"(c[1]), "+f"(c[2]), "+f"(c[3])
        : "r"(a[0]), "r"(a[1]), "r"(a[2]), "r"(a[3]), "r"(b[0]), "r"(b[1]));
}

__device__ __forceinline__ void ldsm4(uint32_t r[4], uint32_t saddr) {
    asm volatile(
        "ldmatrix.sync.aligned.m8n8.x4.shared.b16 {%0,%1,%2,%3}, [%4];"
        : "=r"(r[0]), "=r"(r[1]), "=r"(r[2]), "=r"(r[3]) : "r"(saddr));
}

#define SMS 40                 // smem k-stride in u16 (32 + 8 pad, conflict-free)
#define STAGE_U16 (4 * 128 * SMS)   // Ah|Al|Bh|Bl per stage
#define GEMM_SMEM (2 * STAGE_U16 * 2)  // bytes: 81920

// ---- main-loop body shared textually between mmagemm_bf and mmagemm_wm ----
#define GEMM_MAINLOOP(Abh, Abl, Bbh, Bbl, lda, ldb)                            \
    const int tid = threadIdx.x;                                               \
    const int warp = tid >> 5, lane = tid & 31;                                \
    const int wrm = warp >> 1, wrn = warp & 1;                                 \
    const int g = lane >> 2, q = lane & 3;                                     \
    const int row = tid >> 1, c0 = (tid & 1) * 16;                             \
    const int a_row = lane & 15;                                               \
    const int a_ko  = (lane >> 4) << 3;                                        \
    const int b_row = (lane & 7) + ((lane >> 4) << 3);                         \
    const int b_ko  = ((lane >> 3) & 1) << 3;                                  \
    const uint32_t sbase = (uint32_t)__cvta_generic_to_shared(dyn);            \
    float acc[2][8][4];                                                        \
    _Pragma("unroll")                                                          \
    for (int mt = 0; mt < 2; mt++)                                             \
        _Pragma("unroll")                                                      \
        for (int nt = 0; nt < 8; nt++)                                         \
            _Pragma("unroll")                                                  \
            for (int j = 0; j < 4; j++) acc[mt][nt][j] = 0.f;                  \
    const int nk = K >> 5;                                                     \
    auto load_stage = [&](int st, int k0) {                                    \
        uint16_t* S  = dyn + st * STAGE_U16;                                   \
        uint16_t* Ah = S;                                                      \
        uint16_t* Al = S + 128 * SMS;                                          \
        uint16_t* Bh = S + 2 * 128 * SMS;                                      \
        uint16_t* Bl = S + 3 * 128 * SMS;                                      \
        const size_t aoff = (size_t)(m0 + row) * lda + k0 + c0;                \
        const size_t boff = (size_t)(n0 + row) * ldb + k0 + c0;                \
        cp16(&Ah[row * SMS + c0],     &Abh[aoff]);                             \
        cp16(&Ah[row * SMS + c0 + 8], &Abh[aoff + 8]);                         \
        cp16(&Al[row * SMS + c0],     &Abl[aoff]);                             \
        cp16(&Al[row * SMS + c0 + 8], &Abl[aoff + 8]);                         \
        cp16(&Bh[row * SMS + c0],     &Bbh[boff]);                             \
        cp16(&Bh[row * SMS + c0 + 8], &Bbh[boff + 8]);                         \
        cp16(&Bl[row * SMS + c0],     &Bbl[boff]);                             \
        cp16(&Bl[row * SMS + c0 + 8], &Bbl[boff + 8]);                         \
        cp_commit();                                                           \
    };                                                                         \
    load_stage(0, 0);                                                          \
    for (int kc = 0; kc < nk; kc++) {                                          \
        if (kc + 1 < nk) { load_stage((kc + 1) & 1, (kc + 1) << 5); cp_wait<1>(); } \
        else             { cp_wait<0>(); }                                     \
        __syncthreads();                                                       \
        const uint32_t S   = sbase + (uint32_t)((kc & 1) * STAGE_U16 * 2);     \
        const uint32_t sAh = S;                                                \
        const uint32_t sAl = S + 128 * SMS * 2;                                \
        const uint32_t sBh = S + 2 * 128 * SMS * 2;                            \
        const uint32_t sBl = S + 3 * 128 * SMS * 2;                            \
        _Pragma("unroll")                                                      \
        for (int ks = 0; ks < 32; ks += 16) {                                  \
            uint32_t afh[2][4], afl[2][4];                                     \
            _Pragma("unroll")                                                  \
            for (int mt = 0; mt < 2; mt++) {                                   \
                uint32_t off = (uint32_t)(((wrm * 32 + mt * 16 + a_row) * SMS  \
                                           + ks + a_ko) * 2);                  \
                ldsm4(afh[mt], sAh + off);                                     \
                ldsm4(afl[mt], sAl + off);                                     \
            }                                                                  \
            _Pragma("unroll")                                                  \
            for (int ntp = 0; ntp < 4; ntp++) {                                \
                uint32_t boff2 = (uint32_t)(((wrn * 64 + ntp * 16 + b_row) * SMS \
                                            + ks + b_ko) * 2);                 \
                uint32_t bh[4], bl[4];                                         \
                ldsm4(bh, sBh + boff2);                                        \
                ldsm4(bl, sBl + boff2);                                        \
                _Pragma("unroll")                                              \
                for (int half = 0; half < 2; half++) {                         \
                    int nt = 2 * ntp + half;                                   \
                    _Pragma("unroll")                                          \
                    for (int mt = 0; mt < 2; mt++) {                           \
                        mma16816(acc[mt][nt], afh[mt], &bh[half * 2]);         \
                        mma16816(acc[mt][nt], afh[mt], &bl[half * 2]);         \
                        mma16816(acc[mt][nt], afl[mt], &bh[half * 2]);         \
                    }                                                          \
                }                                                              \
            }                                                                  \
        }                                                                      \
        __syncthreads();                                                       \
    }

template <bool SYM>
__global__ __launch_bounds__(256, 2) void mmagemm_bf(
    const __nv_bfloat16* __restrict__ pAh, const __nv_bfloat16* __restrict__ pAl,
    int lda, size_t sA,
    const __nv_bfloat16* __restrict__ pBh, const __nv_bfloat16* __restrict__ pBl,
    int ldb, size_t sB,
    float* __restrict__ Cp, int ldc, size_t sC, int K)
{
    extern __shared__ __align__(16) uint16_t dyn[];
    const __nv_bfloat16* Abh = pAh + (size_t)blockIdx.z * sA;
    const __nv_bfloat16* Abl = pAl + (size_t)blockIdx.z * sA;
    const __nv_bfloat16* Bbh = pBh + (size_t)blockIdx.z * sB;
    const __nv_bfloat16* Bbl = pBl + (size_t)blockIdx.z * sB;
    float* Cb = Cp + (size_t)blockIdx.z * sC;

    int m0, n0;
    if (SYM) {
        int i = blockIdx.x;
        int bx = (int)((sqrtf(8.f * (float)i + 1.f) - 1.f) * 0.5f);
        while ((bx + 1) * (bx + 2) / 2 <= i) bx++;
        while (bx * (bx + 1) / 2 > i) bx--;
        int by = i - bx * (bx + 1) / 2;
        m0 = by * 128; n0 = bx * 128;
    } else {
        m0 = blockIdx.y * 128; n0 = blockIdx.x * 128;
    }

    GEMM_MAINLOOP(Abh, Abl, Bbh, Bbl, lda, ldb)

#pragma unroll
    for (int mt = 0; mt < 2; mt++) {
        int r0 = m0 + wrm * 32 + mt * 16 + g;
#pragma unroll
        for (int nt = 0; nt < 8; nt++) {
            int cc = n0 + wrn * 64 + nt * 8 + q * 2;
            *(float2*)&Cb[(size_t)r0 * ldc + cc] =
                make_float2(acc[mt][nt][0], acc[mt][nt][1]);
            *(float2*)&Cb[(size_t)(r0 + 8) * ldc + cc] =
                make_float2(acc[mt][nt][2], acc[mt][nt][3]);
            if (SYM && n0 != m0) {
                Cb[(size_t)cc * ldc + r0]           = acc[mt][nt][0];
                Cb[(size_t)(cc + 1) * ldc + r0]     = acc[mt][nt][1];
                Cb[(size_t)cc * ldc + r0 + 8]       = acc[mt][nt][2];
                Cb[(size_t)(cc + 1) * ldc + r0 + 8] = acc[mt][nt][3];
            }
        }
    }
}

// ---- wm GEMM with fused seq reduction: no C output; per-tile per-column ----
// {max,min,sum,sumsq} partials -> g_ep[stat*131072 + mtile*1024 + gcol].
__global__ __launch_bounds__(256, 2) void mmagemm_wm(
    const __nv_bfloat16* __restrict__ pAh, const __nv_bfloat16* __restrict__ pAl,
    int lda,
    const __nv_bfloat16* __restrict__ pBh, const __nv_bfloat16* __restrict__ pBl,
    int ldb, int K)
{
    extern __shared__ __align__(16) uint16_t dyn[];
    const __nv_bfloat16* Abh = pAh;
    const __nv_bfloat16* Abl = pAl;
    const __nv_bfloat16* Bbh = pBh;
    const __nv_bfloat16* Bbl = pBl;
    const int m0 = blockIdx.y * 128, n0 = blockIdx.x * 128;

    GEMM_MAINLOOP(Abh, Abl, Bbh, Bbl, lda, ldb)

    // ---- fused epilogue: reduce tile per-column over its 128 rows ----------
    float* ep = (float*)dyn;   // [wrm 4][col 128][stat 4] = 2048 floats (8KB)
#pragma unroll
    for (int nt = 0; nt < 8; nt++) {
#pragma unroll
        for (int j = 0; j < 2; j++) {
            float v0 = acc[0][nt][j],     v1 = acc[0][nt][j + 2];
            float v2 = acc[1][nt][j],     v3 = acc[1][nt][j + 2];
            float mx = fmaxf(fmaxf(v0, v1), fmaxf(v2, v3));
            float mn = fminf(fminf(v0, v1), fminf(v2, v3));
            float s  = v0 + v1 + v2 + v3;
            float qq = v0 * v0 + v1 * v1 + v2 * v2 + v3 * v3;
#pragma unroll
            for (int off = 16; off >= 4; off >>= 1) {
                mx = fmaxf(mx, __shfl_down_sync(0xffffffffu, mx, off));
                mn = fminf(mn, __shfl_down_sync(0xffffffffu, mn, off));
                s  += __shfl_down_sync(0xffffffffu, s, off);
                qq += __shfl_down_sync(0xffffffffu, qq, off);
            }
            if (lane < 4) {
                int col = wrn * 64 + nt * 8 + lane * 2 + j;
                int base = (wrm * 128 + col) * 4;
                ep[base + 0] = mx; ep[base + 1] = mn;
                ep[base + 2] = s;  ep[base + 3] = qq;
            }
        }
    }
    __syncthreads();
    if (tid < 128) {
        float mx = -FINF, mn = FINF, s = 0.f, qq = 0.f;
#pragma unroll
        for (int w = 0; w < 4; w++) {
            int base = (w * 128 + tid) * 4;
            mx = fmaxf(mx, ep[base + 0]);
            mn = fminf(mn, ep[base + 1]);
            s += ep[base + 2];
            qq += ep[base + 3];
        }
        size_t gi = (size_t)blockIdx.y * 1024 + n0 + tid;
        g_ep[0 * 131072 + gi] = mx;
        g_ep[1 * 131072 + gi] = mn;
        g_ep[2 * 131072 + gi] = s;
        g_ep[3 * 131072 + gi] = qq;
    }
}

// ---- seq_final: combine 16 row-tiles, GN16 stats, emit gvec ----------------
__global__ __launch_bounds__(1024) void seq_final(const float* __restrict__ gmw,
                                                  const float* __restrict__ gmb) {
    __shared__ float fs[1024], fq[1024];
    __shared__ float smu[16], srs[16];
    int b = blockIdx.x, c = threadIdx.x;
    float mx = -FINF, mn = FINF, s = 0.f, qq = 0.f;
#pragma unroll
    for (int t = 0; t < 16; t++) {
        size_t gi = (size_t)((b * 16 + t) << 10) + c;
        mx = fmaxf(mx, g_ep[0 * 131072 + gi]);
        mn = fminf(mn, g_ep[1 * 131072 + gi]);
        s += g_ep[2 * 131072 + gi];
        qq += g_ep[3 * 131072 + gi];
    }
    fs[c] = s; fq[c] = qq;
    __syncthreads();
    if (c < 16) {
        double S = 0.0, Q = 0.0;
        for (int j = 0; j < 64; j++) { S += (double)fs[c * 64 + j]; Q += (double)fq[c * 64 + j]; }
        double cnt = (double)NPTS * 64.0;
        double mu = S / cnt;
        double var = Q / cnt - mu * mu;
        smu[c] = (float)mu;
        srs[c] = rsqrtf((float)var + 1e-5f);
    }
    __syncthreads();
    int g = c >> 6;
    float a = srs[g] * gmw[c];
    float b2 = gmb[c] - smu[g] * a;
    float h = (a >= 0.f) ? mx : mn;
    g_gvec[b * 1024 + c] = leaky02(a * h + b2);
}

// ============ warp-per-query top-20: redux.sync argmin, skewed smem =========
__device__ __forceinline__ uint32_t fkey(float d) {
    uint32_t b = __float_as_uint(d);
    return (b & 0x80000000u) ? ~b : (b | 0x80000000u);
}

__device__ __forceinline__ void topk_from_smem(uint32_t* sd, int row, int lane,
                                               uint32_t bv, int bi) {
    const unsigned FULL = 0xffffffffu;
#pragma unroll 1
    for (int it = 0; it < KNN; it++) {
        uint32_t gmin = __reduce_min_sync(FULL, bv);
        uint32_t cand = (bv == gmin) ? (uint32_t)bi : 0xffffffffu;
        uint32_t gidx = __reduce_min_sync(FULL, cand);
        if (lane == 0) {
            g_idx[(size_t)row * KNN + it] = (int)gidx;
            sd[skew((int)gidx)] = 0xffffffffu;
        }
        __syncwarp();
        int wl = (int)gidx & 31;
        int m0 = wl + 32 * (2 * lane);
        int m1 = m0 + 32;
        uint32_t d0 = sd[skew(m0)];
        uint32_t d1 = sd[skew(m1)];
        uint32_t rv = d0 < d1 ? d0 : d1;
        int      rb = d0 <= d1 ? m0 : m1;
        uint32_t rmin = __reduce_min_sync(FULL, rv);
        uint32_t cnd2 = (rv == rmin) ? (uint32_t)rb : 0xffffffffu;
        uint32_t ridx = __reduce_min_sync(FULL, cnd2);
        if (lane == wl) { bv = rmin; bi = (int)ridx; }
    }
}

__global__ __launch_bounds__(128) void select_gram_kernel() {
    __shared__ uint32_t sd[4][SD_LEN];
    int warp = threadIdx.x >> 5, lane = threadIdx.x & 31;
    int row = blockIdx.x * 4 + warp;
    int b = row >> 11, n = row & 2047;
    const float* drow = g_gram + (size_t)b * NPTS * NPTS + (size_t)n * NPTS;
    float sqn = g_sq[row];
    uint32_t* sdw = sd[warp];
    uint32_t bv = 0xffffffffu; int bi = 0x7fffffff;
#pragma unroll 8
    for (int j = 0; j < 64; j++) {
        int m = lane + 32 * j;
        float d = sqn + g_sq[(b << 11) + m] - 2.f * drow[m];
        uint32_t k = (m == n) ? 0xffffffffu : fkey(d);
        sdw[skew(m)] = k;
        if (k < bv) { bv = k; bi = m; }
    }
    __syncwarp();
    topk_from_smem(sdw, row, lane, bv, bi);
}

__global__ __launch_bounds__(128) void select3_kernel(const float* __restrict__ X) {
    __shared__ uint32_t sd[4][SD_LEN];
    int warp = threadIdx.x >> 5, lane = threadIdx.x & 31;
    int row = blockIdx.x * 4 + warp;
    int b = row >> 11, n = row & 2047;
    const float* Xb = X + (size_t)(b << 11) * 3;
    float xn = Xb[n * 3], yn = Xb[n * 3 + 1], zn = Xb[n * 3 + 2];
    float sqn = g_sq[row];
    uint32_t* sdw = sd[warp];
    uint32_t bv = 0xffffffffu; int bi = 0x7fffffff;
#pragma unroll 4
    for (int j = 0; j < 64; j++) {
        int m = lane + 32 * j;
        float px = Xb[m * 3], py = Xb[m * 3 + 1], pz = Xb[m * 3 + 2];
        float dot = xn * px + yn * py + zn * pz;
        float d = sqn + g_sq[(b << 11) + m] - 2.f * dot;
        uint32_t k = (m == n) ? 0xffffffffu : fkey(d);
        sdw[skew(m)] = k;
        if (k < bv) { bv = k; bi = m; }
    }
    __syncwarp();
    topk_from_smem(sdw, row, lane, bv, bi);
}

// ------------------- weight transforms (pre-split bf16) --------------------
__global__ void wtmp_kernel(const float* __restrict__ w, int C, int O) {
    int i = blockIdx.x * 256 + threadIdx.x;
    int tot = C * 2 * O;
    if (i < tot) {
        int c = i / (2 * O);
        int o = i % (2 * O);
        float v;
        if (o < O) v = w[(size_t)o * (2 * C) + c] - w[(size_t)o * (2 * C) + C + c];
        else       v = w[(size_t)(o - O) * (2 * C) + C + c];
        g_wtmp[i] = v;
    }
}

__global__ void wtmp_bf_all(const float* __restrict__ w2,
                            const float* __restrict__ w3,
                            const float* __restrict__ w4) {
    int i = blockIdx.x * 256 + threadIdx.x;
    if (i >= WTOT) return;
    const float* w; int C, O, rel;
    if (i < WOFF_L3)      { w = w2; C = 64;  O = 64;  rel = i; }
    else if (i < WOFF_L4) { w = w3; C = 64;  O = 128; rel = i - WOFF_L3; }
    else                  { w = w4; C = 128; O = 256; rel = i - WOFF_L4; }
    int o = rel / C, c = rel % C;
    float v;
    if (o < O) v = w[(size_t)o * (2 * C) + c] - w[(size_t)o * (2 * C) + C + c];
    else       v = w[(size_t)(o - O) * (2 * C) + C + c];
    __nv_bfloat16 h, l; split_bf16(v, h, l);
    g_wth[i] = h; g_wtl[i] = l;
}

__global__ void wm_conv_kernel(const float* __restrict__ wm) {
    int i = blockIdx.x * 256 + threadIdx.x;   // 1024*512
    float v = wm[i];
    __nv_bfloat16 h, l; split_bf16(v, h, l);
    g_wmh[i] = h; g_wml[i] = l;
}

// ------------- layer-1 hh (K=3 feature GEMM), 8 rows/block, fused sq --------
__global__ void hh3_kernel(const float* __restrict__ X) {
    __shared__ float w[3 * 128];
    int t = threadIdx.x;   // 128
    w[t] = g_wtmp[t]; w[128 + t] = g_wtmp[128 + t]; w[256 + t] = g_wtmp[256 + t];
    __syncthreads();
    int base = blockIdx.x * 8;
#pragma unroll
    for (int r = 0; r < 8; r++) {
        int row = base + r;
        float x0 = X[row * 3], x1 = X[row * 3 + 1], x2 = X[row * 3 + 2];
        g_hh[(size_t)row * 128 + t] = x0 * w[t] + x1 * w[128 + t] + x2 * w[256 + t];
        if (t == 0) g_sq[row] = x0 * x0 + x1 * x1 + x2 * x2;
    }
}

// ---- fused edge gather: stats + hmax/hmin; 256 threads, 256/O rows/block ---
__global__ __launch_bounds__(256) void edge_gather_kernel(int O) {
    __shared__ int   sidx[4][KNN];
    __shared__ float sacc[4][8];
    const int R = 256 / O;
    int rin = threadIdx.x / O;
    int c   = threadIdx.x % O;
    int row = blockIdx.x * R + rin;
    int b = row >> 11;
    if (c < KNN) sidx[rin][c] = g_idx[(size_t)row * KNN + c];
    if (c < 8)  sacc[rin][c] = 0.f;
    __syncthreads();
    int twoO = 2 * O;
    float hcv = g_hh[(size_t)row * twoO + c];
    size_t bbase = ((size_t)(b << 11)) * twoO + O + c;
    float s = 0.f, q = 0.f, mx = -FINF, mn = FINF;
#pragma unroll
    for (int k = 0; k < KNN; k++) {
        float h = hcv + g_hh[bbase + (size_t)sidx[rin][k] * twoO];
        s += h; q += h * h;
        mx = fmaxf(mx, h); mn = fminf(mn, h);
    }
    g_hmax[(size_t)row * O + c] = mx;
    g_hmin[(size_t)row * O + c] = mn;
    int gsz = O >> 2;
    int rw = gsz < 32 ? gsz : 32;
#pragma unroll
    for (int off = 16; off > 0; off >>= 1) {
        if (off < rw) {
            s += __shfl_down_sync(0xffffffffu, s, off, 32);
            q += __shfl_down_sync(0xffffffffu, q, off, 32);
        }
    }
    int g = c / gsz;
    if ((c & (rw - 1)) == 0 && ((threadIdx.x & 31) % rw) == 0) {
        atomicAdd(&sacc[rin][g * 2 + 0], s);
        atomicAdd(&sacc[rin][g * 2 + 1], q);
    }
    __syncthreads();
    if (c < 8) g_part[(size_t)row * 8 + c] = sacc[rin][c];
}

// ------------------- cross-block stats reduce (edge) ------------------------
__global__ __launch_bounds__(256) void stats_reduce_kernel(int perrow, int ngroups,
                                                           float cnt) {
    __shared__ double ds[256], dq[256];
    int g = blockIdx.x, b = blockIdx.y, t = threadIdx.x;
    double s = 0.0, q = 0.0;
    for (int r = t; r < NPTS; r += 256) {
        size_t base = ((size_t)((b << 11) + r)) * perrow + g * 2;
        s += (double)g_part[base];
        q += (double)g_part[base + 1];
    }
    ds[t] = s; dq[t] = q;
    __syncthreads();
    for (int st = 128; st > 0; st >>= 1) {
        if (t < st) { ds[t] += ds[t + st]; dq[t] += dq[t + st]; }
        __syncthreads();
    }
    if (t == 0) {
        double mu = ds[0] / (double)cnt;
        double var = dq[0] / (double)cnt - mu * mu;
        g_mu[b * ngroups + g] = (float)mu;
        g_rs[b * ngroups + g] = rsqrtf((float)var + 1e-5f);
    }
}

// ---- edge final: affine+leaky of hmax/hmin; bf16 hi/lo out + fused sq ------
__global__ __launch_bounds__(256) void edge_final_kernel(int O, int coff,
                                  const float* __restrict__ gw,
                                  const float* __restrict__ gb) {
    __shared__ float wsum[8];
    const int R = 256 / O;
    int rin = threadIdx.x / O;
    int c   = threadIdx.x % O;
    int row = blockIdx.x * R + rin;
    int b = row >> 11;
    int g = c / (O >> 2);
    float mu = g_mu[b * 4 + g], rs = g_rs[b * 4 + g];
    float a = rs * gw[c];
    float b2 = gb[c] - mu * a;
    float h = (a >= 0.f) ? g_hmax[(size_t)row * O + c] : g_hmin[(size_t)row * O + c];
    float v = leaky02(a * h + b2);
    __nv_bfloat16 vh, vl; split_bf16(v, vh, vl);
    g_ch[(size_t)row * 512 + coff + c] = vh;
    g_cl[(size_t)row * 512 + coff + c] = vl;
    float sq = v * v;
#pragma unroll
    for (int off = 16; off > 0; off >>= 1)
        sq += __shfl_down_sync(0xffffffffu, sq, off);
    int warp = threadIdx.x >> 5;
    if ((threadIdx.x & 31) == 0) wsum[warp] = sq;
    __syncthreads();
    if (c == 0) {
        int w0 = (rin * O) >> 5, nw = O >> 5;
        float s = 0.f;
        for (int i = 0; i < nw; i++) s += wsum[w0 + i];
        g_sq[row] = s;
    }
}

// --------------------------------- MLP head ---------------------------------
__device__ __forceinline__ float bsum256(float v, float* red, int t) {
    red[t] = v; __syncthreads();
    for (int s = 128; s > 0; s >>= 1) {
        if (t < s) red[t] += red[t + s];
        __syncthreads();
    }
    float r = red[0]; __syncthreads();
    return r;
}

__device__ __forceinline__ void ln_leaky(float* buf, int L,
                                         const float* __restrict__ w,
                                         const float* __restrict__ b,
                                         float* red, int t) {
    float s = 0.f, q = 0.f;
    for (int i = t; i < L; i += 256) { float v = buf[i]; s += v; q += v * v; }
    float S = bsum256(s, red, t);
    float Q = bsum256(q, red, t);
    float mu = S / (float)L;
    float var = Q / (float)L - mu * mu;
    float rs = rsqrtf(var + 1e-5f);
    for (int i = t; i < L; i += 256) {
        float v = (buf[i] - mu) * rs * w[i] + b[i];
        buf[i] = leaky02(v);
    }
    __syncthreads();
}

__global__ __launch_bounds__(256) void mlp_kernel(
    const float* __restrict__ fc1w, const float* __restrict__ fc1b,
    const float* __restrict__ ln1w, const float* __restrict__ ln1b,
    const float* __restrict__ fc2w, const float* __restrict__ fc2b,
    const float* __restrict__ ln2w, const float* __restrict__ ln2b,
    const float* __restrict__ fc3w, const float* __restrict__ fc3b,
    const float* __restrict__ ln3w, const float* __restrict__ ln3b,
    const float* __restrict__ fc4w, const float* __restrict__ fc4b,
    float* __restrict__ out)
{
    __shared__ __align__(16) float sin_[1024];
    __shared__ __align__(16) float t1[512];
    __shared__ __align__(16) float t2[256];
    __shared__ __align__(16) float t3[64];
    __shared__ float red[256];
    int b = blockIdx.x, t = threadIdx.x;
    for (int i = t; i < 1024; i += 256) sin_[i] = g_gvec[b * 1024 + i];
    __syncthreads();
    for (int o = t; o < 512; o += 256) {
        float acc = fc1b[o];
        const float4* wr = (const float4*)(fc1w + (size_t)o * 1024);
        const float4* xr = (const float4*)sin_;
        for (int c = 0; c < 256; c++) {
            float4 w4 = wr[c], x4 = xr[c];
            acc += w4.x * x4.x + w4.y * x4.y + w4.z * x4.z + w4.w * x4.w;
        }
        t1[o] = acc;
    }
    __syncthreads();
    ln_leaky(t1, 512, ln1w, ln1b, red, t);
    if (t < 256) {
        float acc = fc2b[t];
        const float4* wr = (const float4*)(fc2w + (size_t)t * 512);
        const float4* xr = (const float4*)t1;
        for (int c = 0; c < 128; c++) {
            float4 w4 = wr[c], x4 = xr[c];
            acc += w4.x * x4.x + w4.y * x4.y + w4.z * x4.z + w4.w * x4.w;
        }
        t2[t] = acc;
    }
    __syncthreads();
    ln_leaky(t2, 256, ln2w, ln2b, red, t);
    if (t < 64) {
        float acc = fc3b[t];
        const float4* wr = (const float4*)(fc3w + (size_t)t * 256);
        const float4* xr = (const float4*)t2;
        for (int c = 0; c < 64; c++) {
            float4 w4 = wr[c], x4 = xr[c];
            acc += w4.x * x4.x + w4.y * x4.y + w4.z * x4.z + w4.w * x4.w;
        }
        t3[t] = acc;
    }
    __syncthreads();
    ln_leaky(t3, 64, ln3w, ln3b, red, t);
    if (t < 2) {
        float acc = fc4b[t];
        for (int c = 0; c < 64; c++) acc += fc4w[t * 64 + c] * t3[c];
        out[b * 2 + t] = acc;
    }
}

// =============================== host driver ================================
extern "C" void kernel_launch(void* const* d_in, const int* in_sizes, int n_in,
                              void* d_out, int out_size)
{
    const float* x    = (const float*)d_in[0];
    const float* w1   = (const float*)d_in[1];
    const float* g1w  = (const float*)d_in[2];
    const float* g1b  = (const float*)d_in[3];
    const float* w2   = (const float*)d_in[4];
    const float* g2w  = (const float*)d_in[5];
    const float* g2b  = (const float*)d_in[6];
    const float* w3   = (const float*)d_in[7];
    const float* g3w  = (const float*)d_in[8];
    const float* g3b  = (const float*)d_in[9];
    const float* w4   = (const float*)d_in[10];
    const float* g4w  = (const float*)d_in[11];
    const float* g4b  = (const float*)d_in[12];
    const float* wm   = (const float*)d_in[13];
    const float* gmw  = (const float*)d_in[14];
    const float* gmb  = (const float*)d_in[15];
    const float* fc1w = (const float*)d_in[16];
    const float* fc1b = (const float*)d_in[17];
    const float* ln1w = (const float*)d_in[18];
    const float* ln1b = (const float*)d_in[19];
    const float* fc2w = (const float*)d_in[20];
    const float* fc2b = (const float*)d_in[21];
    const float* ln2w = (const float*)d_in[22];
    const float* ln2b = (const float*)d_in[23];
    const float* fc3w = (const float*)d_in[24];
    const float* fc3b = (const float*)d_in[25];
    const float* ln3w = (const float*)d_in[26];
    const float* ln3b = (const float*)d_in[27];
    const float* fc4w = (const float*)d_in[28];
    const float* fc4b = (const float*)d_in[29];
    float* out = (float*)d_out;

    float *pGram, *pHH;
    __nv_bfloat16 *pCh, *pCl, *pWth, *pWtl, *pWmh, *pWml;
    cudaGetSymbolAddress((void**)&pGram, g_gram);
    cudaGetSymbolAddress((void**)&pHH,   g_hh);
    cudaGetSymbolAddress((void**)&pCh,   g_ch);
    cudaGetSymbolAddress((void**)&pCl,   g_cl);
    cudaGetSymbolAddress((void**)&pWth,  g_wth);
    cudaGetSymbolAddress((void**)&pWtl,  g_wtl);
    cudaGetSymbolAddress((void**)&pWmh,  g_wmh);
    cudaGetSymbolAddress((void**)&pWml,  g_wml);

    cudaFuncSetAttribute(mmagemm_bf<true>,
                         cudaFuncAttributeMaxDynamicSharedMemorySize, GEMM_SMEM);
    cudaFuncSetAttribute(mmagemm_bf<false>,
                         cudaFuncAttributeMaxDynamicSharedMemorySize, GEMM_SMEM);
    cudaFuncSetAttribute(mmagemm_wm,
                         cudaFuncAttributeMaxDynamicSharedMemorySize, GEMM_SMEM);

    // -------- weight prep (all layers, up front) ---------------------------
    wm_conv_kernel<<<(1024 * 512) / 256, 256>>>(wm);
    wtmp_bf_all<<<(WTOT + 255) / 256, 256>>>(w2, w3, w4);
    wtmp_kernel<<<(3 * 128 + 255) / 256, 256>>>(w1, 3, 64);

    // ---------------- layer 1 (C=3, O=64) ----------------------------------
    hh3_kernel<<<NROWS / 8, 128>>>(x);                 // also writes g_sq
    select3_kernel<<<NROWS / 4, 128>>>(x);
    edge_gather_kernel<<<NROWS / 4, 256>>>(64);
    stats_reduce_kernel<<<dim3(4, NB), 256>>>(8, 4, (float)(NPTS * KNN * 16));
    edge_final_kernel<<<NROWS / 4, 256>>>(64, 0, g1w, g1b);

    // ---------------- layers 2-4 ------------------------------------------
    struct LayerCfg {
        int coffin;   // input slice offset in g_ch/g_cl
        int C; int O; int woff;
        const float* gw; const float* gb; int coff;
    };
    LayerCfg layers[3] = {
        { 0,   64,  64,  WOFF_L2, g2w, g2b, 64  },
        { 64,  64,  128, WOFF_L3, g3w, g3b, 128 },
        { 128, 128, 256, WOFF_L4, g4w, g4b, 256 },
    };

    const int NTILES = (NPTS / 128) * (NPTS / 128 + 1) / 2;   // 136

    for (int l = 0; l < 3; l++) {
        const LayerCfg& L = layers[l];
        mmagemm_bf<true><<<dim3(NTILES, 1, NB), 256, GEMM_SMEM>>>(
            pCh + L.coffin, pCl + L.coffin, 512, (size_t)NPTS * 512,
            pCh + L.coffin, pCl + L.coffin, 512, (size_t)NPTS * 512,
            pGram, NPTS, (size_t)NPTS * NPTS, L.C);
        select_gram_kernel<<<NROWS / 4, 128>>>();
        mmagemm_bf<false><<<dim3(2 * L.O / 128, NROWS / 128, 1), 256, GEMM_SMEM>>>(
            pCh + L.coffin, pCl + L.coffin, 512, 0,
            pWth + L.woff, pWtl + L.woff, L.C, 0,
            pHH, 2 * L.O, 0, L.C);
        int R = 256 / L.O;
        edge_gather_kernel<<<NROWS / R, 256>>>(L.O);
        stats_reduce_kernel<<<dim3(4, NB), 256>>>(8, 4, (float)(NPTS * KNN * (L.O / 4)));
        edge_final_kernel<<<NROWS / R, 256>>>(L.O, L.coff, L.gw, L.gb);
    }

    // mid: wm GEMM fused with full seq pipeline (no hm materialization)
    mmagemm_wm<<<dim3(1024 / 128, NROWS / 128, 1), 256, GEMM_SMEM>>>(
        pCh, pCl, 512, pWmh, pWml, 512, 512);
    seq_final<<<NB, 1024>>>(gmw, gmb);

    // head MLP
    mlp_kernel<<<NB, 256>>>(fc1w, fc1b, ln1w, ln1b,
                            fc2w, fc2b, ln2w, ln2b,
                            fc3w, fc3b, ln3w, ln3b,
                            fc4w, fc4b, out);
}

// round 15
// speedup vs baseline: 1.0855x; 1.0158x over previous
#include <cuda_runtime.h>
#include <cuda_bf16.h>
#include <cstdint>
#include <cstddef>

// ---------------------------------------------------------------------------
// DGCNN pipeline. B=8, N=2048, K=20.
// Round 15: gram + hh GEMMs merged into ONE launch per layer (mmagemm_combo):
// 1-D grid, blocks [0,1088) = symmetric gram tiles (136 x 8 batches), rest =
// hh tiles. Identical per-tile arithmetic to round 14 -> bit-identical output;
// hh time now hides under gram instead of serializing (~50us critical path).
// Everything else as round 14 (922 us, rel_err 3.193e-4).
// ---------------------------------------------------------------------------

#define NPTS   2048
#define NB     8
#define NROWS  (NB*NPTS)   // 16384
#define KNN    20
#define FINF   3.4e38f
#define NTILES_G 136       // (2048/128)*(2048/128+1)/2
#define GRAM_BLOCKS (NTILES_G * NB)   // 1088

// ------------------------- device scratch (no allocs) ----------------------
__device__ float  g_gram[(size_t)NB * NPTS * NPTS];   // reused per layer
__device__ float  g_hh[(size_t)NROWS * 512];          // [rows x 2O], hc | hn
__device__ float  g_hmax[(size_t)NROWS * 256];
__device__ float  g_hmin[(size_t)NROWS * 256];
__device__ float  g_sq[NROWS];
__device__ int    g_idx[(size_t)NROWS * KNN];
__device__ float  g_wtmp[3 * 128];                    // layer-1 fp32 weights
__device__ float  g_part[(size_t)NROWS * 32];         // per-row group partials
__device__ float  g_mu[128];
__device__ float  g_rs[128];
__device__ float  g_ep[4 * 128 * 1024];               // wm tile partials
__device__ float  g_gvec[NB * 1024];
// bf16 split operands
__device__ __align__(16) __nv_bfloat16 g_ch[(size_t)NROWS * 512];   // concat hi
__device__ __align__(16) __nv_bfloat16 g_cl[(size_t)NROWS * 512];   // concat lo
__device__ __align__(16) __nv_bfloat16 g_wth[512 * 192];            // wtmp^T hi, all layers
__device__ __align__(16) __nv_bfloat16 g_wtl[512 * 192];            // wtmp^T lo
__device__ __align__(16) __nv_bfloat16 g_wmh[1024 * 512];           // wm hi
__device__ __align__(16) __nv_bfloat16 g_wml[1024 * 512];           // wm lo

// per-layer weight offsets in g_wth/g_wtl
#define WOFF_L2 0
#define WOFF_L3 8192
#define WOFF_L4 24576
#define WTOT    90112

__device__ __forceinline__ float leaky02(float v) { return v > 0.f ? v : 0.2f * v; }
__device__ __forceinline__ int   skew(int m)      { return m + (m >> 5); }
#define SD_LEN 2112

__device__ __forceinline__ void split_bf16(float v, __nv_bfloat16& h, __nv_bfloat16& l) {
    h = __float2bfloat16(v);
    l = __float2bfloat16(v - __bfloat162float(h));
}

// --------------------------- cp.async helpers -------------------------------
__device__ __forceinline__ void cp16(void* smem, const void* g) {
    uint32_t s = (uint32_t)__cvta_generic_to_shared(smem);
    asm volatile("cp.async.cg.shared.global [%0], [%1], 16;" :: "r"(s), "l"(g));
}
__device__ __forceinline__ void cp_commit() {
    asm volatile("cp.async.commit_group;");
}
template <int N>
__device__ __forceinline__ void cp_wait() {
    asm volatile("cp.async.wait_group %0;" :: "n"(N));
}

// ================= tensor-core GEMM: pre-split bf16, fp32 accum =============
__device__ __forceinline__ void mma16816(float c[4], const uint32_t a[4],
                                         const uint32_t b[2]) {
    asm volatile(
        "mma.sync.aligned.m16n8k16.row.col.f32.bf16.bf16.f32 "
        "{%0,%1,%2,%3}, {%4,%5,%6,%7}, {%8,%9}, {%0,%1,%2,%3};\n"
        : "+f"(c[0]), "+f"(c[1]), "+f"(c[2]), "+f"(c[3])
        : "r"(a[0]), "r"(a[1]), "r"(a[2]), "r"(a[3]), "r"(b[0]), "r"(b[1]));
}

__device__ __forceinline__ void ldsm4(uint32_t r[4], uint32_t saddr) {
    asm volatile(
        "ldmatrix.sync.aligned.m8n8.x4.shared.b16 {%0,%1,%2,%3}, [%4];"
        : "=r"(r[0]), "=r"(r[1]), "=r"(r[2]), "=r"(r[3]) : "r"(saddr));
}

#define SMS 40                 // smem k-stride in u16 (32 + 8 pad, conflict-free)
#define STAGE_U16 (4 * 128 * SMS)   // Ah|Al|Bh|Bl per stage
#define GEMM_SMEM (2 * STAGE_U16 * 2)  // bytes: 81920

// ---- main-loop body shared textually across GEMM kernels -------------------
#define GEMM_MAINLOOP(Abh, Abl, Bbh, Bbl, lda, ldb)                            \
    const int tid = threadIdx.x;                                               \
    const int warp = tid >> 5, lane = tid & 31;                                \
    const int wrm = warp >> 1, wrn = warp & 1;                                 \
    const int g = lane >> 2, q = lane & 3;                                     \
    const int row = tid >> 1, c0 = (tid & 1) * 16;                             \
    const int a_row = lane & 15;                                               \
    const int a_ko  = (lane >> 4) << 3;                                        \
    const int b_row = (lane & 7) + ((lane >> 4) << 3);                         \
    const int b_ko  = ((lane >> 3) & 1) << 3;                                  \
    const uint32_t sbase = (uint32_t)__cvta_generic_to_shared(dyn);            \
    float acc[2][8][4];                                                        \
    _Pragma("unroll")                                                          \
    for (int mt = 0; mt < 2; mt++)                                             \
        _Pragma("unroll")                                                      \
        for (int nt = 0; nt < 8; nt++)                                         \
            _Pragma("unroll")                                                  \
            for (int j = 0; j < 4; j++) acc[mt][nt][j] = 0.f;                  \
    const int nk = K >> 5;                                                     \
    auto load_stage = [&](int st, int k0) {                                    \
        uint16_t* S  = dyn + st * STAGE_U16;                                   \
        uint16_t* Ah = S;                                                      \
        uint16_t* Al = S + 128 * SMS;                                          \
        uint16_t* Bh = S + 2 * 128 * SMS;                                      \
        uint16_t* Bl = S + 3 * 128 * SMS;                                      \
        const size_t aoff = (size_t)(m0 + row) * lda + k0 + c0;                \
        const size_t boff = (size_t)(n0 + row) * ldb + k0 + c0;                \
        cp16(&Ah[row * SMS + c0],     &Abh[aoff]);                             \
        cp16(&Ah[row * SMS + c0 + 8], &Abh[aoff + 8]);                         \
        cp16(&Al[row * SMS + c0],     &Abl[aoff]);                             \
        cp16(&Al[row * SMS + c0 + 8], &Abl[aoff + 8]);                         \
        cp16(&Bh[row * SMS + c0],     &Bbh[boff]);                             \
        cp16(&Bh[row * SMS + c0 + 8], &Bbh[boff + 8]);                         \
        cp16(&Bl[row * SMS + c0],     &Bbl[boff]);                             \
        cp16(&Bl[row * SMS + c0 + 8], &Bbl[boff + 8]);                         \
        cp_commit();                                                           \
    };                                                                         \
    load_stage(0, 0);                                                          \
    for (int kc = 0; kc < nk; kc++) {                                          \
        if (kc + 1 < nk) { load_stage((kc + 1) & 1, (kc + 1) << 5); cp_wait<1>(); } \
        else             { cp_wait<0>(); }                                     \
        __syncthreads();                                                       \
        const uint32_t S   = sbase + (uint32_t)((kc & 1) * STAGE_U16 * 2);     \
        const uint32_t sAh = S;                                                \
        const uint32_t sAl = S + 128 * SMS * 2;                                \
        const uint32_t sBh = S + 2 * 128 * SMS * 2;                            \
        const uint32_t sBl = S + 3 * 128 * SMS * 2;                            \
        _Pragma("unroll")                                                      \
        for (int ks = 0; ks < 32; ks += 16) {                                  \
            uint32_t afh[2][4], afl[2][4];                                     \
            _Pragma("unroll")                                                  \
            for (int mt = 0; mt < 2; mt++) {                                   \
                uint32_t off = (uint32_t)(((wrm * 32 + mt * 16 + a_row) * SMS  \
                                           + ks + a_ko) * 2);                  \
                ldsm4(afh[mt], sAh + off);                                     \
                ldsm4(afl[mt], sAl + off);                                     \
            }                                                                  \
            _Pragma("unroll")                                                  \
            for (int ntp = 0; ntp < 4; ntp++) {                                \
                uint32_t boff2 = (uint32_t)(((wrn * 64 + ntp * 16 + b_row) * SMS \
                                            + ks + b_ko) * 2);                 \
                uint32_t bh[4], bl[4];                                         \
                ldsm4(bh, sBh + boff2);                                        \
                ldsm4(bl, sBl + boff2);                                        \
                _Pragma("unroll")                                              \
                for (int half = 0; half < 2; half++) {                         \
                    int nt = 2 * ntp + half;                                   \
                    _Pragma("unroll")                                          \
                    for (int mt = 0; mt < 2; mt++) {                           \
                        mma16816(acc[mt][nt], afh[mt], &bh[half * 2]);         \
                        mma16816(acc[mt][nt], afh[mt], &bl[half * 2]);         \
                        mma16816(acc[mt][nt], afl[mt], &bh[half * 2]);         \
                    }                                                          \
                }                                                              \
            }                                                                  \
        }                                                                      \
        __syncthreads();                                                       \
    }

// ---- combined gram+hh GEMM: blocks [0,GRAM_BLOCKS) = symmetric gram tiles, -
// ---- remainder = hh tiles (C_hh = feat @ W^T). Same K for both. ------------
__global__ __launch_bounds__(256, 2) void mmagemm_combo(
    const __nv_bfloat16* __restrict__ fh, const __nv_bfloat16* __restrict__ fl,
    int lda, size_t sA,
    const __nv_bfloat16* __restrict__ wh, const __nv_bfloat16* __restrict__ wl,
    int ldw,
    float* __restrict__ gramp, int ldg, size_t sG,
    float* __restrict__ hhp, int ldh,
    int K, int hhx)
{
    extern __shared__ __align__(16) uint16_t dyn[];
    const __nv_bfloat16 *Abh, *Abl, *Bbh, *Bbl;
    float* Cb; int ldb, ldc; bool sym;
    int m0, n0;
    if (blockIdx.x < GRAM_BLOCKS) {
        int i  = blockIdx.x % NTILES_G;
        int bz = blockIdx.x / NTILES_G;
        int bx = (int)((sqrtf(8.f * (float)i + 1.f) - 1.f) * 0.5f);
        while ((bx + 1) * (bx + 2) / 2 <= i) bx++;
        while (bx * (bx + 1) / 2 > i) bx--;
        int by = i - bx * (bx + 1) / 2;
        m0 = by * 128; n0 = bx * 128;
        Abh = fh + (size_t)bz * sA; Abl = fl + (size_t)bz * sA;
        Bbh = Abh; Bbl = Abl; ldb = lda;
        Cb = gramp + (size_t)bz * sG; ldc = ldg; sym = true;
    } else {
        int j  = blockIdx.x - GRAM_BLOCKS;
        int nx = j % hhx, my = j / hhx;
        m0 = my * 128; n0 = nx * 128;
        Abh = fh; Abl = fl;
        Bbh = wh; Bbl = wl; ldb = ldw;
        Cb = hhp; ldc = ldh; sym = false;
    }

    GEMM_MAINLOOP(Abh, Abl, Bbh, Bbl, lda, ldb)

#pragma unroll
    for (int mt = 0; mt < 2; mt++) {
        int r0 = m0 + wrm * 32 + mt * 16 + g;
#pragma unroll
        for (int nt = 0; nt < 8; nt++) {
            int cc = n0 + wrn * 64 + nt * 8 + q * 2;
            *(float2*)&Cb[(size_t)r0 * ldc + cc] =
                make_float2(acc[mt][nt][0], acc[mt][nt][1]);
            *(float2*)&Cb[(size_t)(r0 + 8) * ldc + cc] =
                make_float2(acc[mt][nt][2], acc[mt][nt][3]);
            if (sym && n0 != m0) {
                Cb[(size_t)cc * ldc + r0]           = acc[mt][nt][0];
                Cb[(size_t)(cc + 1) * ldc + r0]     = acc[mt][nt][1];
                Cb[(size_t)cc * ldc + r0 + 8]       = acc[mt][nt][2];
                Cb[(size_t)(cc + 1) * ldc + r0 + 8] = acc[mt][nt][3];
            }
        }
    }
}

// ---- wm GEMM with fused seq reduction (round 14) ----------------------------
__global__ __launch_bounds__(256, 2) void mmagemm_wm(
    const __nv_bfloat16* __restrict__ pAh, const __nv_bfloat16* __restrict__ pAl,
    int lda,
    const __nv_bfloat16* __restrict__ pBh, const __nv_bfloat16* __restrict__ pBl,
    int ldb, int K)
{
    extern __shared__ __align__(16) uint16_t dyn[];
    const __nv_bfloat16* Abh = pAh;
    const __nv_bfloat16* Abl = pAl;
    const __nv_bfloat16* Bbh = pBh;
    const __nv_bfloat16* Bbl = pBl;
    const int m0 = blockIdx.y * 128, n0 = blockIdx.x * 128;

    GEMM_MAINLOOP(Abh, Abl, Bbh, Bbl, lda, ldb)

    float* ep = (float*)dyn;   // [wrm 4][col 128][stat 4]
#pragma unroll
    for (int nt = 0; nt < 8; nt++) {
#pragma unroll
        for (int j = 0; j < 2; j++) {
            float v0 = acc[0][nt][j],     v1 = acc[0][nt][j + 2];
            float v2 = acc[1][nt][j],     v3 = acc[1][nt][j + 2];
            float mx = fmaxf(fmaxf(v0, v1), fmaxf(v2, v3));
            float mn = fminf(fminf(v0, v1), fminf(v2, v3));
            float s  = v0 + v1 + v2 + v3;
            float qq = v0 * v0 + v1 * v1 + v2 * v2 + v3 * v3;
#pragma unroll
            for (int off = 16; off >= 4; off >>= 1) {
                mx = fmaxf(mx, __shfl_down_sync(0xffffffffu, mx, off));
                mn = fminf(mn, __shfl_down_sync(0xffffffffu, mn, off));
                s  += __shfl_down_sync(0xffffffffu, s, off);
                qq += __shfl_down_sync(0xffffffffu, qq, off);
            }
            if (lane < 4) {
                int col = wrn * 64 + nt * 8 + lane * 2 + j;
                int base = (wrm * 128 + col) * 4;
                ep[base + 0] = mx; ep[base + 1] = mn;
                ep[base + 2] = s;  ep[base + 3] = qq;
            }
        }
    }
    __syncthreads();
    if (tid < 128) {
        float mx = -FINF, mn = FINF, s = 0.f, qq = 0.f;
#pragma unroll
        for (int w = 0; w < 4; w++) {
            int base = (w * 128 + tid) * 4;
            mx = fmaxf(mx, ep[base + 0]);
            mn = fminf(mn, ep[base + 1]);
            s += ep[base + 2];
            qq += ep[base + 3];
        }
        size_t gi = (size_t)blockIdx.y * 1024 + n0 + tid;
        g_ep[0 * 131072 + gi] = mx;
        g_ep[1 * 131072 + gi] = mn;
        g_ep[2 * 131072 + gi] = s;
        g_ep[3 * 131072 + gi] = qq;
    }
}

// ---- seq_final: combine 16 row-tiles, GN16 stats, emit gvec ----------------
__global__ __launch_bounds__(1024) void seq_final(const float* __restrict__ gmw,
                                                  const float* __restrict__ gmb) {
    __shared__ float fs[1024], fq[1024];
    __shared__ float smu[16], srs[16];
    int b = blockIdx.x, c = threadIdx.x;
    float mx = -FINF, mn = FINF, s = 0.f, qq = 0.f;
#pragma unroll
    for (int t = 0; t < 16; t++) {
        size_t gi = (size_t)((b * 16 + t) << 10) + c;
        mx = fmaxf(mx, g_ep[0 * 131072 + gi]);
        mn = fminf(mn, g_ep[1 * 131072 + gi]);
        s += g_ep[2 * 131072 + gi];
        qq += g_ep[3 * 131072 + gi];
    }
    fs[c] = s; fq[c] = qq;
    __syncthreads();
    if (c < 16) {
        double S = 0.0, Q = 0.0;
        for (int j = 0; j < 64; j++) { S += (double)fs[c * 64 + j]; Q += (double)fq[c * 64 + j]; }
        double cnt = (double)NPTS * 64.0;
        double mu = S / cnt;
        double var = Q / cnt - mu * mu;
        smu[c] = (float)mu;
        srs[c] = rsqrtf((float)var + 1e-5f);
    }
    __syncthreads();
    int g = c >> 6;
    float a = srs[g] * gmw[c];
    float b2 = gmb[c] - smu[g] * a;
    float h = (a >= 0.f) ? mx : mn;
    g_gvec[b * 1024 + c] = leaky02(a * h + b2);
}

// ============ warp-per-query top-20: redux.sync argmin, skewed smem =========
__device__ __forceinline__ uint32_t fkey(float d) {
    uint32_t b = __float_as_uint(d);
    return (b & 0x80000000u) ? ~b : (b | 0x80000000u);
}

__device__ __forceinline__ void topk_from_smem(uint32_t* sd, int row, int lane,
                                               uint32_t bv, int bi) {
    const unsigned FULL = 0xffffffffu;
#pragma unroll 1
    for (int it = 0; it < KNN; it++) {
        uint32_t gmin = __reduce_min_sync(FULL, bv);
        uint32_t cand = (bv == gmin) ? (uint32_t)bi : 0xffffffffu;
        uint32_t gidx = __reduce_min_sync(FULL, cand);
        if (lane == 0) {
            g_idx[(size_t)row * KNN + it] = (int)gidx;
            sd[skew((int)gidx)] = 0xffffffffu;
        }
        __syncwarp();
        int wl = (int)gidx & 31;
        int m0 = wl + 32 * (2 * lane);
        int m1 = m0 + 32;
        uint32_t d0 = sd[skew(m0)];
        uint32_t d1 = sd[skew(m1)];
        uint32_t rv = d0 < d1 ? d0 : d1;
        int      rb = d0 <= d1 ? m0 : m1;
        uint32_t rmin = __reduce_min_sync(FULL, rv);
        uint32_t cnd2 = (rv == rmin) ? (uint32_t)rb : 0xffffffffu;
        uint32_t ridx = __reduce_min_sync(FULL, cnd2);
        if (lane == wl) { bv = rmin; bi = (int)ridx; }
    }
}

__global__ __launch_bounds__(128) void select_gram_kernel() {
    __shared__ uint32_t sd[4][SD_LEN];
    int warp = threadIdx.x >> 5, lane = threadIdx.x & 31;
    int row = blockIdx.x * 4 + warp;
    int b = row >> 11, n = row & 2047;
    const float* drow = g_gram + (size_t)b * NPTS * NPTS + (size_t)n * NPTS;
    float sqn = g_sq[row];
    uint32_t* sdw = sd[warp];
    uint32_t bv = 0xffffffffu; int bi = 0x7fffffff;
#pragma unroll 8
    for (int j = 0; j < 64; j++) {
        int m = lane + 32 * j;
        float d = sqn + g_sq[(b << 11) + m] - 2.f * drow[m];
        uint32_t k = (m == n) ? 0xffffffffu : fkey(d);
        sdw[skew(m)] = k;
        if (k < bv) { bv = k; bi = m; }
    }
    __syncwarp();
    topk_from_smem(sdw, row, lane, bv, bi);
}

__global__ __launch_bounds__(128) void select3_kernel(const float* __restrict__ X) {
    __shared__ uint32_t sd[4][SD_LEN];
    int warp = threadIdx.x >> 5, lane = threadIdx.x & 31;
    int row = blockIdx.x * 4 + warp;
    int b = row >> 11, n = row & 2047;
    const float* Xb = X + (size_t)(b << 11) * 3;
    float xn = Xb[n * 3], yn = Xb[n * 3 + 1], zn = Xb[n * 3 + 2];
    float sqn = g_sq[row];
    uint32_t* sdw = sd[warp];
    uint32_t bv = 0xffffffffu; int bi = 0x7fffffff;
#pragma unroll 4
    for (int j = 0; j < 64; j++) {
        int m = lane + 32 * j;
        float px = Xb[m * 3], py = Xb[m * 3 + 1], pz = Xb[m * 3 + 2];
        float dot = xn * px + yn * py + zn * pz;
        float d = sqn + g_sq[(b << 11) + m] - 2.f * dot;
        uint32_t k = (m == n) ? 0xffffffffu : fkey(d);
        sdw[skew(m)] = k;
        if (k < bv) { bv = k; bi = m; }
    }
    __syncwarp();
    topk_from_smem(sdw, row, lane, bv, bi);
}

// ------------------- weight transforms (pre-split bf16) --------------------
__global__ void wtmp_kernel(const float* __restrict__ w, int C, int O) {
    int i = blockIdx.x * 256 + threadIdx.x;
    int tot = C * 2 * O;
    if (i < tot) {
        int c = i / (2 * O);
        int o = i % (2 * O);
        float v;
        if (o < O) v = w[(size_t)o * (2 * C) + c] - w[(size_t)o * (2 * C) + C + c];
        else       v = w[(size_t)(o - O) * (2 * C) + C + c];
        g_wtmp[i] = v;
    }
}

__global__ void wtmp_bf_all(const float* __restrict__ w2,
                            const float* __restrict__ w3,
                            const float* __restrict__ w4) {
    int i = blockIdx.x * 256 + threadIdx.x;
    if (i >= WTOT) return;
    const float* w; int C, O, rel;
    if (i < WOFF_L3)      { w = w2; C = 64;  O = 64;  rel = i; }
    else if (i < WOFF_L4) { w = w3; C = 64;  O = 128; rel = i - WOFF_L3; }
    else                  { w = w4; C = 128; O = 256; rel = i - WOFF_L4; }
    int o = rel / C, c = rel % C;
    float v;
    if (o < O) v = w[(size_t)o * (2 * C) + c] - w[(size_t)o * (2 * C) + C + c];
    else       v = w[(size_t)(o - O) * (2 * C) + C + c];
    __nv_bfloat16 h, l; split_bf16(v, h, l);
    g_wth[i] = h; g_wtl[i] = l;
}

__global__ void wm_conv_kernel(const float* __restrict__ wm) {
    int i = blockIdx.x * 256 + threadIdx.x;   // 1024*512
    float v = wm[i];
    __nv_bfloat16 h, l; split_bf16(v, h, l);
    g_wmh[i] = h; g_wml[i] = l;
}

// ------------- layer-1 hh (K=3 feature GEMM), 8 rows/block, fused sq --------
__global__ void hh3_kernel(const float* __restrict__ X) {
    __shared__ float w[3 * 128];
    int t = threadIdx.x;   // 128
    w[t] = g_wtmp[t]; w[128 + t] = g_wtmp[128 + t]; w[256 + t] = g_wtmp[256 + t];
    __syncthreads();
    int base = blockIdx.x * 8;
#pragma unroll
    for (int r = 0; r < 8; r++) {
        int row = base + r;
        float x0 = X[row * 3], x1 = X[row * 3 + 1], x2 = X[row * 3 + 2];
        g_hh[(size_t)row * 128 + t] = x0 * w[t] + x1 * w[128 + t] + x2 * w[256 + t];
        if (t == 0) g_sq[row] = x0 * x0 + x1 * x1 + x2 * x2;
    }
}

// ---- fused edge gather: stats + hmax/hmin; 256 threads, 256/O rows/block ---
__global__ __launch_bounds__(256) void edge_gather_kernel(int O) {
    __shared__ int   sidx[4][KNN];
    __shared__ float sacc[4][8];
    const int R = 256 / O;
    int rin = threadIdx.x / O;
    int c   = threadIdx.x % O;
    int row = blockIdx.x * R + rin;
    int b = row >> 11;
    if (c < KNN) sidx[rin][c] = g_idx[(size_t)row * KNN + c];
    if (c < 8)  sacc[rin][c] = 0.f;
    __syncthreads();
    int twoO = 2 * O;
    float hcv = g_hh[(size_t)row * twoO + c];
    size_t bbase = ((size_t)(b << 11)) * twoO + O + c;
    float s = 0.f, q = 0.f, mx = -FINF, mn = FINF;
#pragma unroll
    for (int k = 0; k < KNN; k++) {
        float h = hcv + g_hh[bbase + (size_t)sidx[rin][k] * twoO];
        s += h; q += h * h;
        mx = fmaxf(mx, h); mn = fminf(mn, h);
    }
    g_hmax[(size_t)row * O + c] = mx;
    g_hmin[(size_t)row * O + c] = mn;
    int gsz = O >> 2;
    int rw = gsz < 32 ? gsz : 32;
#pragma unroll
    for (int off = 16; off > 0; off >>= 1) {
        if (off < rw) {
            s += __shfl_down_sync(0xffffffffu, s, off, 32);
            q += __shfl_down_sync(0xffffffffu, q, off, 32);
        }
    }
    int g = c / gsz;
    if ((c & (rw - 1)) == 0 && ((threadIdx.x & 31) % rw) == 0) {
        atomicAdd(&sacc[rin][g * 2 + 0], s);
        atomicAdd(&sacc[rin][g * 2 + 1], q);
    }
    __syncthreads();
    if (c < 8) g_part[(size_t)row * 8 + c] = sacc[rin][c];
}

// ------------------- cross-block stats reduce (edge) ------------------------
__global__ __launch_bounds__(256) void stats_reduce_kernel(int perrow, int ngroups,
                                                           float cnt) {
    __shared__ double ds[256], dq[256];
    int g = blockIdx.x, b = blockIdx.y, t = threadIdx.x;
    double s = 0.0, q = 0.0;
    for (int r = t; r < NPTS; r += 256) {
        size_t base = ((size_t)((b << 11) + r)) * perrow + g * 2;
        s += (double)g_part[base];
        q += (double)g_part[base + 1];
    }
    ds[t] = s; dq[t] = q;
    __syncthreads();
    for (int st = 128; st > 0; st >>= 1) {
        if (t < st) { ds[t] += ds[t + st]; dq[t] += dq[t + st]; }
        __syncthreads();
    }
    if (t == 0) {
        double mu = ds[0] / (double)cnt;
        double var = dq[0] / (double)cnt - mu * mu;
        g_mu[b * ngroups + g] = (float)mu;
        g_rs[b * ngroups + g] = rsqrtf((float)var + 1e-5f);
    }
}

// ---- edge final: affine+leaky of hmax/hmin; bf16 hi/lo out + fused sq ------
__global__ __launch_bounds__(256) void edge_final_kernel(int O, int coff,
                                  const float* __restrict__ gw,
                                  const float* __restrict__ gb) {
    __shared__ float wsum[8];
    const int R = 256 / O;
    int rin = threadIdx.x / O;
    int c   = threadIdx.x % O;
    int row = blockIdx.x * R + rin;
    int b = row >> 11;
    int g = c / (O >> 2);
    float mu = g_mu[b * 4 + g], rs = g_rs[b * 4 + g];
    float a = rs * gw[c];
    float b2 = gb[c] - mu * a;
    float h = (a >= 0.f) ? g_hmax[(size_t)row * O + c] : g_hmin[(size_t)row * O + c];
    float v = leaky02(a * h + b2);
    __nv_bfloat16 vh, vl; split_bf16(v, vh, vl);
    g_ch[(size_t)row * 512 + coff + c] = vh;
    g_cl[(size_t)row * 512 + coff + c] = vl;
    float sq = v * v;
#pragma unroll
    for (int off = 16; off > 0; off >>= 1)
        sq += __shfl_down_sync(0xffffffffu, sq, off);
    int warp = threadIdx.x >> 5;
    if ((threadIdx.x & 31) == 0) wsum[warp] = sq;
    __syncthreads();
    if (c == 0) {
        int w0 = (rin * O) >> 5, nw = O >> 5;
        float s = 0.f;
        for (int i = 0; i < nw; i++) s += wsum[w0 + i];
        g_sq[row] = s;
    }
}

// --------------------------------- MLP head ---------------------------------
__device__ __forceinline__ float bsum256(float v, float* red, int t) {
    red[t] = v; __syncthreads();
    for (int s = 128; s > 0; s >>= 1) {
        if (t < s) red[t] += red[t + s];
        __syncthreads();
    }
    float r = red[0]; __syncthreads();
    return r;
}

__device__ __forceinline__ void ln_leaky(float* buf, int L,
                                         const float* __restrict__ w,
                                         const float* __restrict__ b,
                                         float* red, int t) {
    float s = 0.f, q = 0.f;
    for (int i = t; i < L; i += 256) { float v = buf[i]; s += v; q += v * v; }
    float S = bsum256(s, red, t);
    float Q = bsum256(q, red, t);
    float mu = S / (float)L;
    float var = Q / (float)L - mu * mu;
    float rs = rsqrtf(var + 1e-5f);
    for (int i = t; i < L; i += 256) {
        float v = (buf[i] - mu) * rs * w[i] + b[i];
        buf[i] = leaky02(v);
    }
    __syncthreads();
}

__global__ __launch_bounds__(256) void mlp_kernel(
    const float* __restrict__ fc1w, const float* __restrict__ fc1b,
    const float* __restrict__ ln1w, const float* __restrict__ ln1b,
    const float* __restrict__ fc2w, const float* __restrict__ fc2b,
    const float* __restrict__ ln2w, const float* __restrict__ ln2b,
    const float* __restrict__ fc3w, const float* __restrict__ fc3b,
    const float* __restrict__ ln3w, const float* __restrict__ ln3b,
    const float* __restrict__ fc4w, const float* __restrict__ fc4b,
    float* __restrict__ out)
{
    __shared__ __align__(16) float sin_[1024];
    __shared__ __align__(16) float t1[512];
    __shared__ __align__(16) float t2[256];
    __shared__ __align__(16) float t3[64];
    __shared__ float red[256];
    int b = blockIdx.x, t = threadIdx.x;
    for (int i = t; i < 1024; i += 256) sin_[i] = g_gvec[b * 1024 + i];
    __syncthreads();
    for (int o = t; o < 512; o += 256) {
        float acc = fc1b[o];
        const float4* wr = (const float4*)(fc1w + (size_t)o * 1024);
        const float4* xr = (const float4*)sin_;
        for (int c = 0; c < 256; c++) {
            float4 w4 = wr[c], x4 = xr[c];
            acc += w4.x * x4.x + w4.y * x4.y + w4.z * x4.z + w4.w * x4.w;
        }
        t1[o] = acc;
    }
    __syncthreads();
    ln_leaky(t1, 512, ln1w, ln1b, red, t);
    if (t < 256) {
        float acc = fc2b[t];
        const float4* wr = (const float4*)(fc2w + (size_t)t * 512);
        const float4* xr = (const float4*)t1;
        for (int c = 0; c < 128; c++) {
            float4 w4 = wr[c], x4 = xr[c];
            acc += w4.x * x4.x + w4.y * x4.y + w4.z * x4.z + w4.w * x4.w;
        }
        t2[t] = acc;
    }
    __syncthreads();
    ln_leaky(t2, 256, ln2w, ln2b, red, t);
    if (t < 64) {
        float acc = fc3b[t];
        const float4* wr = (const float4*)(fc3w + (size_t)t * 256);
        const float4* xr = (const float4*)t2;
        for (int c = 0; c < 64; c++) {
            float4 w4 = wr[c], x4 = xr[c];
            acc += w4.x * x4.x + w4.y * x4.y + w4.z * x4.z + w4.w * x4.w;
        }
        t3[t] = acc;
    }
    __syncthreads();
    ln_leaky(t3, 64, ln3w, ln3b, red, t);
    if (t < 2) {
        float acc = fc4b[t];
        for (int c = 0; c < 64; c++) acc += fc4w[t * 64 + c] * t3[c];
        out[b * 2 + t] = acc;
    }
}

// =============================== host driver ================================
extern "C" void kernel_launch(void* const* d_in, const int* in_sizes, int n_in,
                              void* d_out, int out_size)
{
    const float* x    = (const float*)d_in[0];
    const float* w1   = (const float*)d_in[1];
    const float* g1w  = (const float*)d_in[2];
    const float* g1b  = (const float*)d_in[3];
    const float* w2   = (const float*)d_in[4];
    const float* g2w  = (const float*)d_in[5];
    const float* g2b  = (const float*)d_in[6];
    const float* w3   = (const float*)d_in[7];
    const float* g3w  = (const float*)d_in[8];
    const float* g3b  = (const float*)d_in[9];
    const float* w4   = (const float*)d_in[10];
    const float* g4w  = (const float*)d_in[11];
    const float* g4b  = (const float*)d_in[12];
    const float* wm   = (const float*)d_in[13];
    const float* gmw  = (const float*)d_in[14];
    const float* gmb  = (const float*)d_in[15];
    const float* fc1w = (const float*)d_in[16];
    const float* fc1b = (const float*)d_in[17];
    const float* ln1w = (const float*)d_in[18];
    const float* ln1b = (const float*)d_in[19];
    const float* fc2w = (const float*)d_in[20];
    const float* fc2b = (const float*)d_in[21];
    const float* ln2w = (const float*)d_in[22];
    const float* ln2b = (const float*)d_in[23];
    const float* fc3w = (const float*)d_in[24];
    const float* fc3b = (const float*)d_in[25];
    const float* ln3w = (const float*)d_in[26];
    const float* ln3b = (const float*)d_in[27];
    const float* fc4w = (const float*)d_in[28];
    const float* fc4b = (const float*)d_in[29];
    float* out = (float*)d_out;

    float *pGram, *pHH;
    __nv_bfloat16 *pCh, *pCl, *pWth, *pWtl, *pWmh, *pWml;
    cudaGetSymbolAddress((void**)&pGram, g_gram);
    cudaGetSymbolAddress((void**)&pHH,   g_hh);
    cudaGetSymbolAddress((void**)&pCh,   g_ch);
    cudaGetSymbolAddress((void**)&pCl,   g_cl);
    cudaGetSymbolAddress((void**)&pWth,  g_wth);
    cudaGetSymbolAddress((void**)&pWtl,  g_wtl);
    cudaGetSymbolAddress((void**)&pWmh,  g_wmh);
    cudaGetSymbolAddress((void**)&pWml,  g_wml);

    cudaFuncSetAttribute(mmagemm_combo,
                         cudaFuncAttributeMaxDynamicSharedMemorySize, GEMM_SMEM);
    cudaFuncSetAttribute(mmagemm_wm,
                         cudaFuncAttributeMaxDynamicSharedMemorySize, GEMM_SMEM);

    // -------- weight prep (all layers, up front) ---------------------------
    wm_conv_kernel<<<(1024 * 512) / 256, 256>>>(wm);
    wtmp_bf_all<<<(WTOT + 255) / 256, 256>>>(w2, w3, w4);
    wtmp_kernel<<<(3 * 128 + 255) / 256, 256>>>(w1, 3, 64);

    // ---------------- layer 1 (C=3, O=64) ----------------------------------
    hh3_kernel<<<NROWS / 8, 128>>>(x);                 // also writes g_sq
    select3_kernel<<<NROWS / 4, 128>>>(x);
    edge_gather_kernel<<<NROWS / 4, 256>>>(64);
    stats_reduce_kernel<<<dim3(4, NB), 256>>>(8, 4, (float)(NPTS * KNN * 16));
    edge_final_kernel<<<NROWS / 4, 256>>>(64, 0, g1w, g1b);

    // ---------------- layers 2-4 ------------------------------------------
    struct LayerCfg {
        int coffin;   // input slice offset in g_ch/g_cl
        int C; int O; int woff;
        const float* gw; const float* gb; int coff;
    };
    LayerCfg layers[3] = {
        { 0,   64,  64,  WOFF_L2, g2w, g2b, 64  },
        { 64,  64,  128, WOFF_L3, g3w, g3b, 128 },
        { 128, 128, 256, WOFF_L4, g4w, g4b, 256 },
    };

    for (int l = 0; l < 3; l++) {
        const LayerCfg& L = layers[l];
        int hhx = 2 * L.O / 128;                       // hh n-tiles
        int hhBlocks = hhx * (NROWS / 128);
        // combined gram (sym, per-batch) + hh GEMM in ONE launch
        mmagemm_combo<<<GRAM_BLOCKS + hhBlocks, 256, GEMM_SMEM>>>(
            pCh + L.coffin, pCl + L.coffin, 512, (size_t)NPTS * 512,
            pWth + L.woff, pWtl + L.woff, L.C,
            pGram, NPTS, (size_t)NPTS * NPTS,
            pHH, 2 * L.O,
            L.C, hhx);
        select_gram_kernel<<<NROWS / 4, 128>>>();
        int R = 256 / L.O;
        edge_gather_kernel<<<NROWS / R, 256>>>(L.O);
        stats_reduce_kernel<<<dim3(4, NB), 256>>>(8, 4, (float)(NPTS * KNN * (L.O / 4)));
        edge_final_kernel<<<NROWS / R, 256>>>(L.O, L.coff, L.gw, L.gb);
    }

    // mid: wm GEMM fused with full seq pipeline (no hm materialization)
    mmagemm_wm<<<dim3(1024 / 128, NROWS / 128, 1), 256, GEMM_SMEM>>>(
        pCh, pCl, 512, pWmh, pWml, 512, 512);
    seq_final<<<NB, 1024>>>(gmw, gmb);

    // head MLP
    mlp_kernel<<<NB, 256>>>(fc1w, fc1b, ln1w, ln1b,
                            fc2w, fc2b, ln2w, ln2b,
                            fc3w, fc3b, ln3w, ln3b,
                            fc4w, fc4b, out);
}